// round 7
// baseline (speedup 1.0000x reference)
#include <cuda_runtime.h>
#include <cuda_fp16.h>
#include <cstdint>
#include <math.h>

#define DIM    7168
#define NEXP   256
#define NTOK   16384
#define TOPKN  8
#define NGRP   8
#define TOPG   4

#define BM     64
#define KCH    32
#define NCH    (DIM / KCH)        // 224
#define NSTAGE 4

#define TROW   80                 // 32 fp16 = 64B + 16B pad (odd 16B stride: conflict-free)
#define A_TILE (64 * TROW)        // 5120
#define B_TILE (256 * TROW)       // 20480
#define OFF_AH 0
#define OFF_AL A_TILE
#define OFF_BH (2 * A_TILE)
#define OFF_BL (2 * A_TILE + B_TILE)
#define STAGEB (2 * A_TILE + 2 * B_TILE)   // 51200
#define SMEMB  (NSTAGE * STAGEB)           // 204800

#define W_SCALE   64.0f
#define INV_SCALE 0.015625f

// Global scratch (allocation-free): pre-split fp16 operands + logits.
__device__ __align__(16) __half g_xh[(size_t)NTOK * DIM];
__device__ __align__(16) __half g_xl[(size_t)NTOK * DIM];
__device__ __align__(16) __half g_wh[(size_t)NEXP * DIM];
__device__ __align__(16) __half g_wl[(size_t)NEXP * DIM];
__device__ __align__(16) float  g_logits[(size_t)NTOK * NEXP];

// ---------------------------------------------------------------------------
// helpers
// ---------------------------------------------------------------------------
__device__ __forceinline__ uint32_t smem_u32(const void* p) {
    uint32_t a;
    asm("{ .reg .u64 t; cvta.to.shared.u64 t, %1; cvt.u32.u64 %0, t; }" : "=r"(a) : "l"(p));
    return a;
}

__device__ __forceinline__ void cp16(uint32_t dst, const void* src) {
    asm volatile("cp.async.cg.shared.global [%0], [%1], 16;" :: "r"(dst), "l"(src));
}
#define CP_COMMIT() asm volatile("cp.async.commit_group;" ::: "memory")
#define CP_WAIT2()  asm volatile("cp.async.wait_group 2;" ::: "memory")

#define LDMATRIX4(r, addr) \
    asm volatile("ldmatrix.sync.aligned.m8n8.x4.shared.b16 {%0,%1,%2,%3}, [%4];" \
        : "=r"((r)[0]), "=r"((r)[1]), "=r"((r)[2]), "=r"((r)[3]) : "r"(addr))

#define MMA16816F16(d, a, b0v, b1v) \
    asm volatile("mma.sync.aligned.m16n8k16.row.col.f32.f16.f16.f32 " \
        "{%0,%1,%2,%3}, {%4,%5,%6,%7}, {%8,%9}, {%0,%1,%2,%3};" \
        : "+f"((d)[0]), "+f"((d)[1]), "+f"((d)[2]), "+f"((d)[3]) \
        : "r"((a)[0]), "r"((a)[1]), "r"((a)[2]), "r"((a)[3]), "r"(b0v), "r"(b1v))

// Fast2Sum fold (exact PTX so the compiler can't simplify)
__device__ __forceinline__ void fast2sum(float& hi, float& lo) {
    float s, z;
    asm("add.rn.f32 %0, %1, %2;" : "=f"(s) : "f"(hi), "f"(lo));
    asm("sub.rn.f32 %0, %1, %2;" : "=f"(z) : "f"(s), "f"(hi));
    asm("sub.rn.f32 %0, %1, %2;" : "=f"(lo) : "f"(lo), "f"(z));
    hi = s;
}

// ---------------------------------------------------------------------------
// Prep: exact 2-way fp16 split of scaled fp32 stream.
// ---------------------------------------------------------------------------
__global__ void __launch_bounds__(256)
split_prep_kernel(const float* __restrict__ src,
                  __half* __restrict__ hO, __half* __restrict__ lO,
                  float scale, int n4)
{
    const float4* s4 = reinterpret_cast<const float4*>(src);
    int i = blockIdx.x * blockDim.x + threadIdx.x;
    const int stride = gridDim.x * blockDim.x;
    for (; i < n4; i += stride) {
        float4 v = s4[i];
        v.x *= scale; v.y *= scale; v.z *= scale; v.w *= scale;
        __half2 h0 = __floats2half2_rn(v.x, v.y);
        __half2 h1 = __floats2half2_rn(v.z, v.w);
        float2 f0 = __half22float2(h0), f1 = __half22float2(h1);
        __half2 l0 = __floats2half2_rn(v.x - f0.x, v.y - f0.y);
        __half2 l1 = __floats2half2_rn(v.z - f1.x, v.w - f1.y);
        uint2 hv, lv;
        hv.x = *reinterpret_cast<uint32_t*>(&h0);
        hv.y = *reinterpret_cast<uint32_t*>(&h1);
        lv.x = *reinterpret_cast<uint32_t*>(&l0);
        lv.y = *reinterpret_cast<uint32_t*>(&l1);
        *reinterpret_cast<uint2*>(hO + 4 * (size_t)i) = hv;
        *reinterpret_cast<uint2*>(lO + 4 * (size_t)i) = lv;
    }
}

// ---------------------------------------------------------------------------
// GEMM: logits = x @ (64*w)^T / 64.  BM=64 x BN=256 (full expert dim per CTA,
// x read once from DRAM).  fp16 HMMA, 3 passes (hh+hl+lh), 4-stage cp.async.
// ---------------------------------------------------------------------------
extern __shared__ char dynsmem[];

__global__ void __launch_bounds__(256)
gemm_hmma_kernel()
{
    const int bm   = blockIdx.x;
    const int tid  = threadIdx.x;
    const int lane = tid & 31;
    const int wid  = tid >> 5;
    const int warp_m = wid >> 2;     // 0..1 -> token rows warp_m*32
    const int warp_n = wid & 3;      // 0..3 -> expert cols warp_n*64

    const uint32_t smem = smem_u32(dynsmem);

    const __half* xh_b = g_xh + (size_t)(bm * BM) * DIM;
    const __half* xl_b = g_xl + (size_t)(bm * BM) * DIM;

    float acc[2][8][4];
    float hiv[2][8][4];
    #pragma unroll
    for (int a = 0; a < 2; a++)
        #pragma unroll
        for (int n = 0; n < 8; n++)
            #pragma unroll
            for (int r = 0; r < 4; r++) { acc[a][n][r] = 0.0f; hiv[a][n][r] = 0.0f; }

    auto issue_chunk = [&](int c) {
        const uint32_t sb = smem + (uint32_t)(c % NSTAGE) * STAGEB;
        const int kb = c * KCH;
        // A tiles: 64 rows x 4 segs = 256 slots (1 per thread)
        {
            const int r = tid >> 2, s = tid & 3;
            const uint32_t d = sb + r * TROW + s * 16;
            const size_t go = (size_t)r * DIM + kb + s * 8;
            cp16(d + OFF_AH, xh_b + go);
            cp16(d + OFF_AL, xl_b + go);
        }
        // B tiles: 256 rows x 4 segs = 1024 slots (4 per thread); full w
        #pragma unroll
        for (int t = 0; t < 4; t++) {
            const int q = tid + t * 256;
            const int r = q >> 2, s = q & 3;
            const uint32_t d = sb + r * TROW + s * 16;
            const size_t go = (size_t)r * DIM + kb + s * 8;
            cp16(d + OFF_BH, g_wh + go);
            cp16(d + OFF_BL, g_wl + go);
        }
    };

    issue_chunk(0); CP_COMMIT();
    issue_chunk(1); CP_COMMIT();
    issue_chunk(2); CP_COMMIT();

    for (int c = 0; c < NCH; ++c) {
        CP_WAIT2();                       // chunk c complete
        __syncthreads();                  // data visible; stage (c+3)%4 reads done

        if (c + 3 < NCH) issue_chunk(c + 3);
        CP_COMMIT();

        const uint32_t stage = smem + (uint32_t)(c % NSTAGE) * STAGEB;

        #pragma unroll
        for (int ks = 0; ks < 2; ++ks) {
            uint32_t ah[2][4], al[2][4];
            #pragma unroll
            for (int amz = 0; amz < 2; ++amz) {
                const int row = warp_m * 32 + amz * 16 + (lane & 15);
                const int u   = ks * 2 + (lane >> 4);
                const uint32_t ad = stage + row * TROW + u * 16;
                LDMATRIX4(ah[amz], ad + OFF_AH);
                LDMATRIX4(al[amz], ad + OFF_AL);
            }
            #pragma unroll
            for (int pair = 0; pair < 4; ++pair) {
                const int brow = warp_n * 64 + pair * 16 + (lane & 7) + ((lane >> 4) << 3);
                const int u    = ks * 2 + ((lane >> 3) & 1);
                const uint32_t bd = stage + brow * TROW + u * 16;
                uint32_t bh[4], bl[4];
                LDMATRIX4(bh, bd + OFF_BH);
                LDMATRIX4(bl, bd + OFF_BL);
                #pragma unroll
                for (int amz = 0; amz < 2; ++amz)
                    #pragma unroll
                    for (int bo = 0; bo < 2; ++bo) {
                        float* d = acc[amz][pair * 2 + bo];
                        MMA16816F16(d, ah[amz], bh[2*bo], bh[2*bo+1]);   // hh
                        MMA16816F16(d, ah[amz], bl[2*bo], bl[2*bo+1]);   // hl
                        MMA16816F16(d, al[amz], bh[2*bo], bh[2*bo+1]);   // lh
                    }
            }
        }

        if ((c & 3) == 3) {               // fold every 128 K (as round 6)
            #pragma unroll
            for (int a = 0; a < 2; a++)
                #pragma unroll
                for (int n = 0; n < 8; n++)
                    #pragma unroll
                    for (int r = 0; r < 4; r++)
                        fast2sum(hiv[a][n][r], acc[a][n][r]);
        }
    }

    // ---- write logits (undo W scale) ----
    #pragma unroll
    for (int amz = 0; amz < 2; ++amz) {
        const int token = bm * BM + warp_m * 32 + amz * 16 + (lane >> 2);
        #pragma unroll
        for (int n = 0; n < 8; ++n) {
            const int expert = warp_n * 64 + n * 8 + (lane & 3) * 2;
            float d0 = (hiv[amz][n][0] + acc[amz][n][0]) * INV_SCALE;
            float d1 = (hiv[amz][n][1] + acc[amz][n][1]) * INV_SCALE;
            float d2 = (hiv[amz][n][2] + acc[amz][n][2]) * INV_SCALE;
            float d3 = (hiv[amz][n][3] + acc[amz][n][3]) * INV_SCALE;
            *reinterpret_cast<float2*>(&g_logits[(size_t)token * NEXP + expert]) =
                make_float2(d0, d1);
            *reinterpret_cast<float2*>(&g_logits[(size_t)(token + 8) * NEXP + expert]) =
                make_float2(d2, d3);
        }
    }
}

// ---------------------------------------------------------------------------
// Accurate exp (~2 ulp), immune to fast-math.
// ---------------------------------------------------------------------------
__device__ __forceinline__ float exp_acc(float xin) {
    float xc = fminf(fmaxf(xin, -30.0f), 30.0f);
    float k = rintf(xc * 1.4426950408889634f);
    float r = fmaf(k, -0.693359375f, xc);
    r = fmaf(k, 2.12194440054690e-4f, r);
    float p = 1.98412698e-4f;
    p = fmaf(p, r, 1.38888889e-3f);
    p = fmaf(p, r, 8.33333333e-3f);
    p = fmaf(p, r, 4.16666667e-2f);
    p = fmaf(p, r, 1.66666667e-1f);
    p = fmaf(p, r, 5.0e-1f);
    p = fmaf(p, r, 1.0f);
    p = fmaf(p, r, 1.0f);
    int ik = (int)k;
    float sc2 = __int_as_float((ik + 127) << 23);
    return p * sc2;
}

// ---------------------------------------------------------------------------
// Epilogue: WARP per token (no __syncthreads).  8 logits per lane.
// Semantics identical to verified block version (all tie rules preserved).
// ---------------------------------------------------------------------------
__global__ void __launch_bounds__(256)
gate_epilogue_warp(const float* __restrict__ bias,
                   float* __restrict__ out_w,
                   float* __restrict__ out_idx,
                   int write_idx)
{
    const unsigned FULL = 0xffffffffu;
    const int warp = threadIdx.x >> 5;
    const int lane = threadIdx.x & 31;
    const int t = blockIdx.x * 8 + warp;

    const float* row = &g_logits[(size_t)t * NEXP + lane * 8];
    float4 q0 = *reinterpret_cast<const float4*>(row);
    float4 q1 = *reinterpret_cast<const float4*>(row + 4);
    float4 b0 = *reinterpret_cast<const float4*>(&bias[lane * 8]);
    float4 b1 = *reinterpret_cast<const float4*>(&bias[lane * 8 + 4]);

    float lg[8] = {q0.x, q0.y, q0.z, q0.w, q1.x, q1.y, q1.z, q1.w};
    float bs[8] = {b0.x, b0.y, b0.z, b0.w, b1.x, b1.y, b1.z, b1.w};

    float sc[8], s[8];
    #pragma unroll
    for (int i = 0; i < 8; i++) {
        sc[i] = __fdiv_rn(1.0f, 1.0f + exp_acc(-lg[i]));
        s[i]  = sc[i] + bs[i];
    }

    // --- per-lane top-2 of 8, then merge across the 4-lane quad (one group) ---
    float v1 = -INFINITY, v2 = -INFINITY;
    #pragma unroll
    for (int i = 0; i < 8; i++) {
        if (s[i] > v1)      { v2 = v1; v1 = s[i]; }
        else if (s[i] > v2) { v2 = s[i]; }
    }
    #pragma unroll
    for (int o = 1; o <= 2; o <<= 1) {
        float u1 = __shfl_xor_sync(FULL, v1, o);
        float u2 = __shfl_xor_sync(FULL, v2, o);
        if (u1 > v1) { v2 = fmaxf(v1, u2); v1 = u1; }
        else         { v2 = fmaxf(v2, u1); }
    }
    const float gs = v1 + v2;       // all lanes of the quad agree

    // --- top-4 groups via rank (ties -> lower group index) ---
    float gv[8];
    #pragma unroll
    for (int g = 0; g < 8; g++) gv[g] = __shfl_sync(FULL, gs, g * 4);
    const int g0 = lane >> 2;
    int rank = 0;
    #pragma unroll
    for (int g = 0; g < 8; g++)
        rank += (gv[g] > gv[g0]) || (gv[g] == gv[g0] && g < g0);
    const bool keep = (rank < TOPG);

    float mv[8];
    #pragma unroll
    for (int i = 0; i < 8; i++) mv[i] = keep ? s[i] : -INFINITY;

    // --- masked top-8 (value desc, index asc) ---
    unsigned live = 0xffu;
    float rsc[8]; int ridx[8];
    float wsum = 0.0f;
    #pragma unroll
    for (int r = 0; r < TOPKN; r++) {
        float bv = -INFINITY, bsc2 = 0.0f;
        int bi = -1;
        #pragma unroll
        for (int i = 0; i < 8; i++) {
            if (((live >> i) & 1u) && mv[i] > bv) { bv = mv[i]; bsc2 = sc[i]; bi = i; }
        }
        int gidx = (bi >= 0) ? (lane * 8 + bi) : (1 << 30);
        float cv = bv, csc = bsc2;
        int ci = gidx;
        #pragma unroll
        for (int o = 16; o > 0; o >>= 1) {
            float ov  = __shfl_xor_sync(FULL, cv, o);
            int   oi  = __shfl_xor_sync(FULL, ci, o);
            float osc = __shfl_xor_sync(FULL, csc, o);
            if (ov > cv || (ov == cv && oi < ci)) { cv = ov; ci = oi; csc = osc; }
        }
        rsc[r] = csc; ridx[r] = ci;
        wsum += csc;
        if (lane == (ci >> 3)) live &= ~(1u << (ci & 7));
    }

    #pragma unroll
    for (int r = 0; r < TOPKN; r++) {
        if (lane == r) {
            out_w[(size_t)t * TOPKN + r] = __fdiv_rn(rsc[r], wsum) * 2.5f;
            if (write_idx) out_idx[(size_t)t * TOPKN + r] = (float)ridx[r];
        }
    }
}

// ---------------------------------------------------------------------------
extern "C" void kernel_launch(void* const* d_in, const int* in_sizes, int n_in,
                              void* d_out, int out_size)
{
    const float* x    = (const float*)d_in[0];   // [T, 7168]
    const float* w    = (const float*)d_in[1];   // [256, 7168]
    const float* bias = (const float*)d_in[2];   // [256]

    const int T = in_sizes[0] / DIM;             // 16384

    __half *p_xh, *p_xl, *p_wh, *p_wl;
    cudaGetSymbolAddress((void**)&p_xh, g_xh);
    cudaGetSymbolAddress((void**)&p_xl, g_xl);
    cudaGetSymbolAddress((void**)&p_wh, g_wh);
    cudaGetSymbolAddress((void**)&p_wl, g_wl);

    split_prep_kernel<<<4096, 256>>>(x, p_xh, p_xl, 1.0f, T * DIM / 4);
    split_prep_kernel<<<256, 256>>>(w, p_wh, p_wl, W_SCALE, NEXP * DIM / 4);

    cudaFuncSetAttribute(gemm_hmma_kernel,
                         cudaFuncAttributeMaxDynamicSharedMemorySize, SMEMB);

    gemm_hmma_kernel<<<T / BM, 256, SMEMB>>>();

    float* out = (float*)d_out;
    const int write_idx = (out_size >= 2 * T * TOPKN) ? 1 : 0;
    gate_epilogue_warp<<<T / 8, 256>>>(bias, out, out + (size_t)T * TOPKN, write_idx);
}

// round 8
// speedup vs baseline: 1.1835x; 1.1835x over previous
#include <cuda_runtime.h>
#include <cuda_fp16.h>
#include <cstdint>
#include <math.h>

#define DIM    7168
#define NEXP   256
#define NTOK   16384
#define TOPKN  8
#define NGRP   8
#define TOPG   4

#define BM     128
#define BN     128
#define KCH    64                 // K per chunk
#define NCH    (DIM / KCH)        // 112
#define NSTAGE 3

#define TROW   144                // 64 fp16 = 128B + 16B pad (conflict-free ldmatrix)
#define TILEB  (128 * TROW)       // 18432 B
#define STAGEB (4 * TILEB)        // Ah Al Bh Bl = 73728 B
#define SMEMB  (NSTAGE * STAGEB)  // 221184 B

#define OFF_AH 0
#define OFF_AL TILEB
#define OFF_BH (2 * TILEB)
#define OFF_BL (3 * TILEB)

#define W_SCALE   64.0f
#define INV_SCALE 0.015625f

// Global scratch (allocation-free): pre-split fp16 operands + logits.
__device__ __align__(16) __half g_xh[(size_t)NTOK * DIM];
__device__ __align__(16) __half g_xl[(size_t)NTOK * DIM];
__device__ __align__(16) __half g_wh[(size_t)NEXP * DIM];
__device__ __align__(16) __half g_wl[(size_t)NEXP * DIM];
__device__ __align__(16) float  g_logits[(size_t)NTOK * NEXP];

// ---------------------------------------------------------------------------
// helpers
// ---------------------------------------------------------------------------
__device__ __forceinline__ uint32_t smem_u32(const void* p) {
    uint32_t a;
    asm("{ .reg .u64 t; cvta.to.shared.u64 t, %1; cvt.u32.u64 %0, t; }" : "=r"(a) : "l"(p));
    return a;
}

__device__ __forceinline__ void cp16(uint32_t dst, const void* src) {
    asm volatile("cp.async.cg.shared.global [%0], [%1], 16;" :: "r"(dst), "l"(src));
}
#define CP_COMMIT() asm volatile("cp.async.commit_group;" ::: "memory")
#define CP_WAIT1()  asm volatile("cp.async.wait_group 1;" ::: "memory")

#define LDMATRIX4(r, addr) \
    asm volatile("ldmatrix.sync.aligned.m8n8.x4.shared.b16 {%0,%1,%2,%3}, [%4];" \
        : "=r"((r)[0]), "=r"((r)[1]), "=r"((r)[2]), "=r"((r)[3]) : "r"(addr))

#define MMA16816F16(d, a, b0v, b1v) \
    asm volatile("mma.sync.aligned.m16n8k16.row.col.f32.f16.f16.f32 " \
        "{%0,%1,%2,%3}, {%4,%5,%6,%7}, {%8,%9}, {%0,%1,%2,%3};" \
        : "+f"((d)[0]), "+f"((d)[1]), "+f"((d)[2]), "+f"((d)[3]) \
        : "r"((a)[0]), "r"((a)[1]), "r"((a)[2]), "r"((a)[3]), "r"(b0v), "r"(b1v))

// Fast2Sum fold (exact PTX so the compiler can't simplify)
__device__ __forceinline__ void fast2sum(float& hi, float& lo) {
    float s, z;
    asm("add.rn.f32 %0, %1, %2;" : "=f"(s) : "f"(hi), "f"(lo));
    asm("sub.rn.f32 %0, %1, %2;" : "=f"(z) : "f"(s), "f"(hi));
    asm("sub.rn.f32 %0, %1, %2;" : "=f"(lo) : "f"(lo), "f"(z));
    hi = s;
}

// ---------------------------------------------------------------------------
// Prep: exact 2-way fp16 split of scaled fp32 stream.
// ---------------------------------------------------------------------------
__global__ void __launch_bounds__(256)
split_prep_kernel(const float* __restrict__ src,
                  __half* __restrict__ hO, __half* __restrict__ lO,
                  float scale, int n4)
{
    const float4* s4 = reinterpret_cast<const float4*>(src);
    int i = blockIdx.x * blockDim.x + threadIdx.x;
    const int stride = gridDim.x * blockDim.x;
    for (; i < n4; i += stride) {
        float4 v = s4[i];
        v.x *= scale; v.y *= scale; v.z *= scale; v.w *= scale;
        __half2 h0 = __floats2half2_rn(v.x, v.y);
        __half2 h1 = __floats2half2_rn(v.z, v.w);
        float2 f0 = __half22float2(h0), f1 = __half22float2(h1);
        __half2 l0 = __floats2half2_rn(v.x - f0.x, v.y - f0.y);
        __half2 l1 = __floats2half2_rn(v.z - f1.x, v.w - f1.y);
        uint2 hv, lv;
        hv.x = *reinterpret_cast<uint32_t*>(&h0);
        hv.y = *reinterpret_cast<uint32_t*>(&h1);
        lv.x = *reinterpret_cast<uint32_t*>(&l0);
        lv.y = *reinterpret_cast<uint32_t*>(&l1);
        *reinterpret_cast<uint2*>(hO + 4 * (size_t)i) = hv;
        *reinterpret_cast<uint2*>(lO + 4 * (size_t)i) = lv;
    }
}

// ---------------------------------------------------------------------------
// GEMM: logits = x @ (64*w)^T / 64.  fp16 HMMA, 3 passes (hh+hl+lh),
// cp.async 3-stage pipeline on pre-split fp16 operands, Fast2Sum accumulate.
// Round-6 configuration (fastest measured); grid swapped so the two bn-CTAs
// of each bm are launch-adjacent -> x tile L2 reuse.
// ---------------------------------------------------------------------------
extern __shared__ char dynsmem[];

__global__ void __launch_bounds__(256)
gemm_hmma_kernel()
{
    const int bn   = blockIdx.x;     // 0..1  (fast-varying -> adjacent CTAs share x)
    const int bm   = blockIdx.y;     // 0..127
    const int tid  = threadIdx.x;
    const int lane = tid & 31;
    const int wid  = tid >> 5;
    const int warp_m = wid >> 1;     // 0..3 -> token rows warp_m*32
    const int warp_n = wid & 1;      // 0..1 -> expert cols warp_n*64

    const uint32_t smem = smem_u32(dynsmem);

    const __half* xh_b = g_xh + (size_t)(bm * BM) * DIM;
    const __half* xl_b = g_xl + (size_t)(bm * BM) * DIM;
    const __half* wh_b = g_wh + (size_t)(bn * BN) * DIM;
    const __half* wl_b = g_wl + (size_t)(bn * BN) * DIM;

    float acc[2][8][4];
    float hiv[2][8][4];
    #pragma unroll
    for (int a = 0; a < 2; a++)
        #pragma unroll
        for (int n = 0; n < 8; n++)
            #pragma unroll
            for (int r = 0; r < 4; r++) { acc[a][n][r] = 0.0f; hiv[a][n][r] = 0.0f; }

    // per-thread cp.async slots: q -> (row, 16B segment)
    auto issue_chunk = [&](int c) {
        const uint32_t sb = smem + (uint32_t)(c % NSTAGE) * STAGEB;
        const int kb = c * KCH;
        #pragma unroll
        for (int t = 0; t < 4; t++) {
            const int q = tid + t * 256;
            const int r = q >> 3;
            const int s = q & 7;
            const uint32_t d = sb + r * TROW + s * 16;
            const size_t go = (size_t)r * DIM + kb + s * 8;
            cp16(d + OFF_AH, xh_b + go);
            cp16(d + OFF_AL, xl_b + go);
            cp16(d + OFF_BH, wh_b + go);
            cp16(d + OFF_BL, wl_b + go);
        }
    };

    issue_chunk(0); CP_COMMIT();
    issue_chunk(1); CP_COMMIT();

    for (int c = 0; c < NCH; ++c) {
        CP_WAIT1();                       // group for chunk c complete
        __syncthreads();                  // data visible; prior stage reads done

        if (c + 2 < NCH) issue_chunk(c + 2);
        CP_COMMIT();                      // always commit (keeps group count in sync)

        const uint32_t stage = smem + (uint32_t)(c % NSTAGE) * STAGEB;

        #pragma unroll
        for (int ks = 0; ks < 4; ++ks) {
            uint32_t ah[2][4], al[2][4];
            #pragma unroll
            for (int amz = 0; amz < 2; ++amz) {
                const int row = warp_m * 32 + amz * 16 + (lane & 15);
                const int u   = ks * 2 + (lane >> 4);
                const uint32_t ad = stage + row * TROW + u * 16;
                LDMATRIX4(ah[amz], ad + OFF_AH);
                LDMATRIX4(al[amz], ad + OFF_AL);
            }
            #pragma unroll
            for (int pair = 0; pair < 4; ++pair) {
                const int brow = warp_n * 64 + pair * 16 + (lane & 7) + ((lane >> 4) << 3);
                const int u    = ks * 2 + ((lane >> 3) & 1);
                const uint32_t bd = stage + brow * TROW + u * 16;
                uint32_t bh[4], bl[4];
                LDMATRIX4(bh, bd + OFF_BH);
                LDMATRIX4(bl, bd + OFF_BL);
                #pragma unroll
                for (int amz = 0; amz < 2; ++amz)
                    #pragma unroll
                    for (int bo = 0; bo < 2; ++bo) {
                        float* d = acc[amz][pair * 2 + bo];
                        MMA16816F16(d, ah[amz], bh[2*bo], bh[2*bo+1]);   // hh
                        MMA16816F16(d, ah[amz], bl[2*bo], bl[2*bo+1]);   // hl
                        MMA16816F16(d, al[amz], bh[2*bo], bh[2*bo+1]);   // lh
                    }
            }
        }

        if (c & 1) {
            #pragma unroll
            for (int a = 0; a < 2; a++)
                #pragma unroll
                for (int n = 0; n < 8; n++)
                    #pragma unroll
                    for (int r = 0; r < 4; r++)
                        fast2sum(hiv[a][n][r], acc[a][n][r]);
        }
    }

    // ---- write logits (undo W scale) ----
    #pragma unroll
    for (int amz = 0; amz < 2; ++amz) {
        const int token = bm * BM + warp_m * 32 + amz * 16 + (lane >> 2);
        #pragma unroll
        for (int n = 0; n < 8; ++n) {
            const int expert = bn * BN + warp_n * 64 + n * 8 + (lane & 3) * 2;
            float d0 = (hiv[amz][n][0] + acc[amz][n][0]) * INV_SCALE;
            float d1 = (hiv[amz][n][1] + acc[amz][n][1]) * INV_SCALE;
            float d2 = (hiv[amz][n][2] + acc[amz][n][2]) * INV_SCALE;
            float d3 = (hiv[amz][n][3] + acc[amz][n][3]) * INV_SCALE;
            *reinterpret_cast<float2*>(&g_logits[(size_t)token * NEXP + expert]) =
                make_float2(d0, d1);
            *reinterpret_cast<float2*>(&g_logits[(size_t)(token + 8) * NEXP + expert]) =
                make_float2(d2, d3);
        }
    }
}

// ---------------------------------------------------------------------------
// Accurate exp (~2 ulp), immune to fast-math.
// ---------------------------------------------------------------------------
__device__ __forceinline__ float exp_acc(float xin) {
    float xc = fminf(fmaxf(xin, -30.0f), 30.0f);
    float k = rintf(xc * 1.4426950408889634f);
    float r = fmaf(k, -0.693359375f, xc);
    r = fmaf(k, 2.12194440054690e-4f, r);
    float p = 1.98412698e-4f;
    p = fmaf(p, r, 1.38888889e-3f);
    p = fmaf(p, r, 8.33333333e-3f);
    p = fmaf(p, r, 4.16666667e-2f);
    p = fmaf(p, r, 1.66666667e-1f);
    p = fmaf(p, r, 5.0e-1f);
    p = fmaf(p, r, 1.0f);
    p = fmaf(p, r, 1.0f);
    int ik = (int)k;
    float sc2 = __int_as_float((ik + 127) << 23);
    return p * sc2;
}

// ---------------------------------------------------------------------------
// Epilogue: WARP per token (no __syncthreads) — verified in round 7.
// ---------------------------------------------------------------------------
__global__ void __launch_bounds__(256)
gate_epilogue_warp(const float* __restrict__ bias,
                   float* __restrict__ out_w,
                   float* __restrict__ out_idx,
                   int write_idx)
{
    const unsigned FULL = 0xffffffffu;
    const int warp = threadIdx.x >> 5;
    const int lane = threadIdx.x & 31;
    const int t = blockIdx.x * 8 + warp;

    const float* row = &g_logits[(size_t)t * NEXP + lane * 8];
    float4 q0 = *reinterpret_cast<const float4*>(row);
    float4 q1 = *reinterpret_cast<const float4*>(row + 4);
    float4 b0 = *reinterpret_cast<const float4*>(&bias[lane * 8]);
    float4 b1 = *reinterpret_cast<const float4*>(&bias[lane * 8 + 4]);

    float lg[8] = {q0.x, q0.y, q0.z, q0.w, q1.x, q1.y, q1.z, q1.w};
    float bs[8] = {b0.x, b0.y, b0.z, b0.w, b1.x, b1.y, b1.z, b1.w};

    float sc[8], s[8];
    #pragma unroll
    for (int i = 0; i < 8; i++) {
        sc[i] = __fdiv_rn(1.0f, 1.0f + exp_acc(-lg[i]));
        s[i]  = sc[i] + bs[i];
    }

    // --- per-lane top-2 of 8, then merge across the 4-lane quad (one group) ---
    float v1 = -INFINITY, v2 = -INFINITY;
    #pragma unroll
    for (int i = 0; i < 8; i++) {
        if (s[i] > v1)      { v2 = v1; v1 = s[i]; }
        else if (s[i] > v2) { v2 = s[i]; }
    }
    #pragma unroll
    for (int o = 1; o <= 2; o <<= 1) {
        float u1 = __shfl_xor_sync(FULL, v1, o);
        float u2 = __shfl_xor_sync(FULL, v2, o);
        if (u1 > v1) { v2 = fmaxf(v1, u2); v1 = u1; }
        else         { v2 = fmaxf(v2, u1); }
    }
    const float gs = v1 + v2;       // all lanes of the quad agree

    // --- top-4 groups via rank (ties -> lower group index) ---
    float gv[8];
    #pragma unroll
    for (int g = 0; g < 8; g++) gv[g] = __shfl_sync(FULL, gs, g * 4);
    const int g0 = lane >> 2;
    int rank = 0;
    #pragma unroll
    for (int g = 0; g < 8; g++)
        rank += (gv[g] > gv[g0]) || (gv[g] == gv[g0] && g < g0);
    const bool keep = (rank < TOPG);

    float mv[8];
    #pragma unroll
    for (int i = 0; i < 8; i++) mv[i] = keep ? s[i] : -INFINITY;

    // --- masked top-8 (value desc, index asc) ---
    unsigned live = 0xffu;
    float rsc[8]; int ridx[8];
    float wsum = 0.0f;
    #pragma unroll
    for (int r = 0; r < TOPKN; r++) {
        float bv = -INFINITY, bsc2 = 0.0f;
        int bi = -1;
        #pragma unroll
        for (int i = 0; i < 8; i++) {
            if (((live >> i) & 1u) && mv[i] > bv) { bv = mv[i]; bsc2 = sc[i]; bi = i; }
        }
        int gidx = (bi >= 0) ? (lane * 8 + bi) : (1 << 30);
        float cv = bv, csc = bsc2;
        int ci = gidx;
        #pragma unroll
        for (int o = 16; o > 0; o >>= 1) {
            float ov  = __shfl_xor_sync(FULL, cv, o);
            int   oi  = __shfl_xor_sync(FULL, ci, o);
            float osc = __shfl_xor_sync(FULL, csc, o);
            if (ov > cv || (ov == cv && oi < ci)) { cv = ov; ci = oi; csc = osc; }
        }
        rsc[r] = csc; ridx[r] = ci;
        wsum += csc;
        if (lane == (ci >> 3)) live &= ~(1u << (ci & 7));
    }

    #pragma unroll
    for (int r = 0; r < TOPKN; r++) {
        if (lane == r) {
            out_w[(size_t)t * TOPKN + r] = __fdiv_rn(rsc[r], wsum) * 2.5f;
            if (write_idx) out_idx[(size_t)t * TOPKN + r] = (float)ridx[r];
        }
    }
}

// ---------------------------------------------------------------------------
extern "C" void kernel_launch(void* const* d_in, const int* in_sizes, int n_in,
                              void* d_out, int out_size)
{
    const float* x    = (const float*)d_in[0];   // [T, 7168]
    const float* w    = (const float*)d_in[1];   // [256, 7168]
    const float* bias = (const float*)d_in[2];   // [256]

    const int T = in_sizes[0] / DIM;             // 16384

    __half *p_xh, *p_xl, *p_wh, *p_wl;
    cudaGetSymbolAddress((void**)&p_xh, g_xh);
    cudaGetSymbolAddress((void**)&p_xl, g_xl);
    cudaGetSymbolAddress((void**)&p_wh, g_wh);
    cudaGetSymbolAddress((void**)&p_wl, g_wl);

    split_prep_kernel<<<4096, 256>>>(x, p_xh, p_xl, 1.0f, T * DIM / 4);
    split_prep_kernel<<<256, 256>>>(w, p_wh, p_wl, W_SCALE, NEXP * DIM / 4);

    cudaFuncSetAttribute(gemm_hmma_kernel,
                         cudaFuncAttributeMaxDynamicSharedMemorySize, SMEMB);

    dim3 grid(NEXP / BN, T / BM);                // (2, 128): bn fast-varying
    gemm_hmma_kernel<<<grid, 256, SMEMB>>>();

    float* out = (float*)d_out;
    const int write_idx = (out_size >= 2 * T * TOPKN) ? 1 : 0;
    gate_epilogue_warp<<<T / 8, 256>>>(bias, out, out + (size_t)T * TOPKN, write_idx);
}

// round 9
// speedup vs baseline: 1.1843x; 1.0007x over previous
#include <cuda_runtime.h>
#include <cuda_fp16.h>
#include <cstdint>
#include <math.h>

#define DIM    7168
#define NEXP   256
#define NTOK   16384
#define TOPKN  8
#define NGRP   8
#define TOPG   4

#define BM     128
#define BN     128
#define KCH    64                 // K per chunk
#define NCH    (DIM / KCH)        // 112
#define NSTAGE 3

#define TROW   144                // 64 fp16 = 128B + 16B pad (conflict-free ldmatrix)
#define TILEB  (128 * TROW)       // 18432 B
#define STAGEB (4 * TILEB)        // Ah Al Bh Bl = 73728 B
#define SMEMB  (NSTAGE * STAGEB)  // 221184 B

#define OFF_AH 0
#define OFF_AL TILEB
#define OFF_BH (2 * TILEB)
#define OFF_BL (3 * TILEB)

#define W_SCALE   64.0f
#define INV_SCALE 0.015625f

// Global scratch (allocation-free): pre-split fp16 operands + logits.
__device__ __align__(16) __half g_xh[(size_t)NTOK * DIM];
__device__ __align__(16) __half g_xl[(size_t)NTOK * DIM];
__device__ __align__(16) __half g_wh[(size_t)NEXP * DIM];
__device__ __align__(16) __half g_wl[(size_t)NEXP * DIM];
__device__ __align__(16) float  g_logits[(size_t)NTOK * NEXP];

// ---------------------------------------------------------------------------
// helpers
// ---------------------------------------------------------------------------
__device__ __forceinline__ uint32_t smem_u32(const void* p) {
    uint32_t a;
    asm("{ .reg .u64 t; cvta.to.shared.u64 t, %1; cvt.u32.u64 %0, t; }" : "=r"(a) : "l"(p));
    return a;
}

__device__ __forceinline__ void cp16(uint32_t dst, const void* src) {
    asm volatile("cp.async.cg.shared.global [%0], [%1], 16;" :: "r"(dst), "l"(src));
}
#define CP_COMMIT() asm volatile("cp.async.commit_group;" ::: "memory")
#define CP_WAIT1()  asm volatile("cp.async.wait_group 1;" ::: "memory")

#define LDMATRIX4(r, addr) \
    asm volatile("ldmatrix.sync.aligned.m8n8.x4.shared.b16 {%0,%1,%2,%3}, [%4];" \
        : "=r"((r)[0]), "=r"((r)[1]), "=r"((r)[2]), "=r"((r)[3]) : "r"(addr))

#define MMA16816F16(d, a, b0v, b1v) \
    asm volatile("mma.sync.aligned.m16n8k16.row.col.f32.f16.f16.f32 " \
        "{%0,%1,%2,%3}, {%4,%5,%6,%7}, {%8,%9}, {%0,%1,%2,%3};" \
        : "+f"((d)[0]), "+f"((d)[1]), "+f"((d)[2]), "+f"((d)[3]) \
        : "r"((a)[0]), "r"((a)[1]), "r"((a)[2]), "r"((a)[3]), "r"(b0v), "r"(b1v))

// Fast2Sum fold (exact PTX so the compiler can't simplify)
__device__ __forceinline__ void fast2sum(float& hi, float& lo) {
    float s, z;
    asm("add.rn.f32 %0, %1, %2;" : "=f"(s) : "f"(hi), "f"(lo));
    asm("sub.rn.f32 %0, %1, %2;" : "=f"(z) : "f"(s), "f"(hi));
    asm("sub.rn.f32 %0, %1, %2;" : "=f"(lo) : "f"(lo), "f"(z));
    hi = s;
}

// ---------------------------------------------------------------------------
// Prep: exact 2-way fp16 split of scaled fp32 stream.
// ---------------------------------------------------------------------------
__global__ void __launch_bounds__(256)
split_prep_kernel(const float* __restrict__ src,
                  __half* __restrict__ hO, __half* __restrict__ lO,
                  float scale, int n4)
{
    const float4* s4 = reinterpret_cast<const float4*>(src);
    int i = blockIdx.x * blockDim.x + threadIdx.x;
    const int stride = gridDim.x * blockDim.x;
    for (; i < n4; i += stride) {
        float4 v = s4[i];
        v.x *= scale; v.y *= scale; v.z *= scale; v.w *= scale;
        __half2 h0 = __floats2half2_rn(v.x, v.y);
        __half2 h1 = __floats2half2_rn(v.z, v.w);
        float2 f0 = __half22float2(h0), f1 = __half22float2(h1);
        __half2 l0 = __floats2half2_rn(v.x - f0.x, v.y - f0.y);
        __half2 l1 = __floats2half2_rn(v.z - f1.x, v.w - f1.y);
        uint2 hv, lv;
        hv.x = *reinterpret_cast<uint32_t*>(&h0);
        hv.y = *reinterpret_cast<uint32_t*>(&h1);
        lv.x = *reinterpret_cast<uint32_t*>(&l0);
        lv.y = *reinterpret_cast<uint32_t*>(&l1);
        *reinterpret_cast<uint2*>(hO + 4 * (size_t)i) = hv;
        *reinterpret_cast<uint2*>(lO + 4 * (size_t)i) = lv;
    }
}

// ---------------------------------------------------------------------------
// GEMM: logits = x @ (64*w)^T / 64.  fp16 HMMA, 3 passes (hh+hl+lh),
// cp.async 3-stage pipeline, Fast2Sum accumulate.
// Round-8 config; inner loop reordered PASS-MAJOR over 2-pair blocks so
// consecutive MMAs on the same accumulator are 8 issues apart (dependency
// chain no longer paces the tensor pipe).
// ---------------------------------------------------------------------------
extern __shared__ char dynsmem[];

__global__ void __launch_bounds__(256)
gemm_hmma_kernel()
{
    const int bn   = blockIdx.x;     // 0..1  (fast-varying -> adjacent CTAs share x)
    const int bm   = blockIdx.y;     // 0..127
    const int tid  = threadIdx.x;
    const int lane = tid & 31;
    const int wid  = tid >> 5;
    const int warp_m = wid >> 1;     // 0..3 -> token rows warp_m*32
    const int warp_n = wid & 1;      // 0..1 -> expert cols warp_n*64

    const uint32_t smem = smem_u32(dynsmem);

    const __half* xh_b = g_xh + (size_t)(bm * BM) * DIM;
    const __half* xl_b = g_xl + (size_t)(bm * BM) * DIM;
    const __half* wh_b = g_wh + (size_t)(bn * BN) * DIM;
    const __half* wl_b = g_wl + (size_t)(bn * BN) * DIM;

    float acc[2][8][4];
    float hiv[2][8][4];
    #pragma unroll
    for (int a = 0; a < 2; a++)
        #pragma unroll
        for (int n = 0; n < 8; n++)
            #pragma unroll
            for (int r = 0; r < 4; r++) { acc[a][n][r] = 0.0f; hiv[a][n][r] = 0.0f; }

    // per-thread cp.async slots: q -> (row, 16B segment)
    auto issue_chunk = [&](int c) {
        const uint32_t sb = smem + (uint32_t)(c % NSTAGE) * STAGEB;
        const int kb = c * KCH;
        #pragma unroll
        for (int t = 0; t < 4; t++) {
            const int q = tid + t * 256;
            const int r = q >> 3;
            const int s = q & 7;
            const uint32_t d = sb + r * TROW + s * 16;
            const size_t go = (size_t)r * DIM + kb + s * 8;
            cp16(d + OFF_AH, xh_b + go);
            cp16(d + OFF_AL, xl_b + go);
            cp16(d + OFF_BH, wh_b + go);
            cp16(d + OFF_BL, wl_b + go);
        }
    };

    issue_chunk(0); CP_COMMIT();
    issue_chunk(1); CP_COMMIT();

    for (int c = 0; c < NCH; ++c) {
        CP_WAIT1();                       // group for chunk c complete
        __syncthreads();                  // data visible; prior stage reads done

        if (c + 2 < NCH) issue_chunk(c + 2);
        CP_COMMIT();                      // always commit (keeps group count in sync)

        const uint32_t stage = smem + (uint32_t)(c % NSTAGE) * STAGEB;

        #pragma unroll
        for (int ks = 0; ks < 4; ++ks) {
            uint32_t ah[2][4], al[2][4];
            #pragma unroll
            for (int amz = 0; amz < 2; ++amz) {
                const int row = warp_m * 32 + amz * 16 + (lane & 15);
                const int u   = ks * 2 + (lane >> 4);
                const uint32_t ad = stage + row * TROW + u * 16;
                LDMATRIX4(ah[amz], ad + OFF_AH);
                LDMATRIX4(al[amz], ad + OFF_AL);
            }
            // 2-pair blocks: load B frags for both pairs, then pass-major MMAs
            #pragma unroll
            for (int pb = 0; pb < 4; pb += 2) {
                uint32_t bh2[2][4], bl2[2][4];
                #pragma unroll
                for (int pp = 0; pp < 2; ++pp) {
                    const int pair = pb + pp;
                    const int brow = warp_n * 64 + pair * 16 + (lane & 7) + ((lane >> 4) << 3);
                    const int u    = ks * 2 + ((lane >> 3) & 1);
                    const uint32_t bd = stage + brow * TROW + u * 16;
                    LDMATRIX4(bh2[pp], bd + OFF_BH);
                    LDMATRIX4(bl2[pp], bd + OFF_BL);
                }
                // pass hh: same-acc distance 8; then hl; then lh
                #pragma unroll
                for (int pp = 0; pp < 2; ++pp)
                    #pragma unroll
                    for (int amz = 0; amz < 2; ++amz)
                        #pragma unroll
                        for (int bo = 0; bo < 2; ++bo)
                            MMA16816F16(acc[amz][(pb + pp) * 2 + bo],
                                        ah[amz], bh2[pp][2*bo], bh2[pp][2*bo+1]);
                #pragma unroll
                for (int pp = 0; pp < 2; ++pp)
                    #pragma unroll
                    for (int amz = 0; amz < 2; ++amz)
                        #pragma unroll
                        for (int bo = 0; bo < 2; ++bo)
                            MMA16816F16(acc[amz][(pb + pp) * 2 + bo],
                                        ah[amz], bl2[pp][2*bo], bl2[pp][2*bo+1]);
                #pragma unroll
                for (int pp = 0; pp < 2; ++pp)
                    #pragma unroll
                    for (int amz = 0; amz < 2; ++amz)
                        #pragma unroll
                        for (int bo = 0; bo < 2; ++bo)
                            MMA16816F16(acc[amz][(pb + pp) * 2 + bo],
                                        al[amz], bh2[pp][2*bo], bh2[pp][2*bo+1]);
            }
        }

        if (c & 1) {
            #pragma unroll
            for (int a = 0; a < 2; a++)
                #pragma unroll
                for (int n = 0; n < 8; n++)
                    #pragma unroll
                    for (int r = 0; r < 4; r++)
                        fast2sum(hiv[a][n][r], acc[a][n][r]);
        }
    }

    // ---- write logits (undo W scale) ----
    #pragma unroll
    for (int amz = 0; amz < 2; ++amz) {
        const int token = bm * BM + warp_m * 32 + amz * 16 + (lane >> 2);
        #pragma unroll
        for (int n = 0; n < 8; ++n) {
            const int expert = bn * BN + warp_n * 64 + n * 8 + (lane & 3) * 2;
            float d0 = (hiv[amz][n][0] + acc[amz][n][0]) * INV_SCALE;
            float d1 = (hiv[amz][n][1] + acc[amz][n][1]) * INV_SCALE;
            float d2 = (hiv[amz][n][2] + acc[amz][n][2]) * INV_SCALE;
            float d3 = (hiv[amz][n][3] + acc[amz][n][3]) * INV_SCALE;
            *reinterpret_cast<float2*>(&g_logits[(size_t)token * NEXP + expert]) =
                make_float2(d0, d1);
            *reinterpret_cast<float2*>(&g_logits[(size_t)(token + 8) * NEXP + expert]) =
                make_float2(d2, d3);
        }
    }
}

// ---------------------------------------------------------------------------
// Accurate exp (~2 ulp), immune to fast-math.
// ---------------------------------------------------------------------------
__device__ __forceinline__ float exp_acc(float xin) {
    float xc = fminf(fmaxf(xin, -30.0f), 30.0f);
    float k = rintf(xc * 1.4426950408889634f);
    float r = fmaf(k, -0.693359375f, xc);
    r = fmaf(k, 2.12194440054690e-4f, r);
    float p = 1.98412698e-4f;
    p = fmaf(p, r, 1.38888889e-3f);
    p = fmaf(p, r, 8.33333333e-3f);
    p = fmaf(p, r, 4.16666667e-2f);
    p = fmaf(p, r, 1.66666667e-1f);
    p = fmaf(p, r, 5.0e-1f);
    p = fmaf(p, r, 1.0f);
    p = fmaf(p, r, 1.0f);
    int ik = (int)k;
    float sc2 = __int_as_float((ik + 127) << 23);
    return p * sc2;
}

// ---------------------------------------------------------------------------
// Epilogue: WARP per token (no __syncthreads) — verified rounds 7/8.
// ---------------------------------------------------------------------------
__global__ void __launch_bounds__(256)
gate_epilogue_warp(const float* __restrict__ bias,
                   float* __restrict__ out_w,
                   float* __restrict__ out_idx,
                   int write_idx)
{
    const unsigned FULL = 0xffffffffu;
    const int warp = threadIdx.x >> 5;
    const int lane = threadIdx.x & 31;
    const int t = blockIdx.x * 8 + warp;

    const float* row = &g_logits[(size_t)t * NEXP + lane * 8];
    float4 q0 = *reinterpret_cast<const float4*>(row);
    float4 q1 = *reinterpret_cast<const float4*>(row + 4);
    float4 b0 = *reinterpret_cast<const float4*>(&bias[lane * 8]);
    float4 b1 = *reinterpret_cast<const float4*>(&bias[lane * 8 + 4]);

    float lg[8] = {q0.x, q0.y, q0.z, q0.w, q1.x, q1.y, q1.z, q1.w};
    float bs[8] = {b0.x, b0.y, b0.z, b0.w, b1.x, b1.y, b1.z, b1.w};

    float sc[8], s[8];
    #pragma unroll
    for (int i = 0; i < 8; i++) {
        sc[i] = __fdiv_rn(1.0f, 1.0f + exp_acc(-lg[i]));
        s[i]  = sc[i] + bs[i];
    }

    // --- per-lane top-2 of 8, then merge across the 4-lane quad (one group) ---
    float v1 = -INFINITY, v2 = -INFINITY;
    #pragma unroll
    for (int i = 0; i < 8; i++) {
        if (s[i] > v1)      { v2 = v1; v1 = s[i]; }
        else if (s[i] > v2) { v2 = s[i]; }
    }
    #pragma unroll
    for (int o = 1; o <= 2; o <<= 1) {
        float u1 = __shfl_xor_sync(FULL, v1, o);
        float u2 = __shfl_xor_sync(FULL, v2, o);
        if (u1 > v1) { v2 = fmaxf(v1, u2); v1 = u1; }
        else         { v2 = fmaxf(v2, u1); }
    }
    const float gs = v1 + v2;       // all lanes of the quad agree

    // --- top-4 groups via rank (ties -> lower group index) ---
    float gv[8];
    #pragma unroll
    for (int g = 0; g < 8; g++) gv[g] = __shfl_sync(FULL, gs, g * 4);
    const int g0 = lane >> 2;
    int rank = 0;
    #pragma unroll
    for (int g = 0; g < 8; g++)
        rank += (gv[g] > gv[g0]) || (gv[g] == gv[g0] && g < g0);
    const bool keep = (rank < TOPG);

    float mv[8];
    #pragma unroll
    for (int i = 0; i < 8; i++) mv[i] = keep ? s[i] : -INFINITY;

    // --- masked top-8 (value desc, index asc) ---
    unsigned live = 0xffu;
    float rsc[8]; int ridx[8];
    float wsum = 0.0f;
    #pragma unroll
    for (int r = 0; r < TOPKN; r++) {
        float bv = -INFINITY, bsc2 = 0.0f;
        int bi = -1;
        #pragma unroll
        for (int i = 0; i < 8; i++) {
            if (((live >> i) & 1u) && mv[i] > bv) { bv = mv[i]; bsc2 = sc[i]; bi = i; }
        }
        int gidx = (bi >= 0) ? (lane * 8 + bi) : (1 << 30);
        float cv = bv, csc = bsc2;
        int ci = gidx;
        #pragma unroll
        for (int o = 16; o > 0; o >>= 1) {
            float ov  = __shfl_xor_sync(FULL, cv, o);
            int   oi  = __shfl_xor_sync(FULL, ci, o);
            float osc = __shfl_xor_sync(FULL, csc, o);
            if (ov > cv || (ov == cv && oi < ci)) { cv = ov; ci = oi; csc = osc; }
        }
        rsc[r] = csc; ridx[r] = ci;
        wsum += csc;
        if (lane == (ci >> 3)) live &= ~(1u << (ci & 7));
    }

    #pragma unroll
    for (int r = 0; r < TOPKN; r++) {
        if (lane == r) {
            out_w[(size_t)t * TOPKN + r] = __fdiv_rn(rsc[r], wsum) * 2.5f;
            if (write_idx) out_idx[(size_t)t * TOPKN + r] = (float)ridx[r];
        }
    }
}

// ---------------------------------------------------------------------------
extern "C" void kernel_launch(void* const* d_in, const int* in_sizes, int n_in,
                              void* d_out, int out_size)
{
    const float* x    = (const float*)d_in[0];   // [T, 7168]
    const float* w    = (const float*)d_in[1];   // [256, 7168]
    const float* bias = (const float*)d_in[2];   // [256]

    const int T = in_sizes[0] / DIM;             // 16384

    __half *p_xh, *p_xl, *p_wh, *p_wl;
    cudaGetSymbolAddress((void**)&p_xh, g_xh);
    cudaGetSymbolAddress((void**)&p_xl, g_xl);
    cudaGetSymbolAddress((void**)&p_wh, g_wh);
    cudaGetSymbolAddress((void**)&p_wl, g_wl);

    split_prep_kernel<<<4096, 256>>>(x, p_xh, p_xl, 1.0f, T * DIM / 4);
    split_prep_kernel<<<256, 256>>>(w, p_wh, p_wl, W_SCALE, NEXP * DIM / 4);

    cudaFuncSetAttribute(gemm_hmma_kernel,
                         cudaFuncAttributeMaxDynamicSharedMemorySize, SMEMB);

    dim3 grid(NEXP / BN, T / BM);                // (2, 128): bn fast-varying
    gemm_hmma_kernel<<<grid, 256, SMEMB>>>();

    float* out = (float*)d_out;
    const int write_idx = (out_size >= 2 * T * TOPKN) ? 1 : 0;
    gate_epilogue_warp<<<T / 8, 256>>>(bias, out, out + (size_t)T * TOPKN, write_idx);
}

// round 10
// speedup vs baseline: 1.2885x; 1.0880x over previous
#include <cuda_runtime.h>
#include <cuda_fp16.h>
#include <cstdint>
#include <math.h>

#define DIM    7168
#define NEXP   256
#define NTOK   16384
#define TOPKN  8
#define NGRP   8
#define TOPG   4

#define BM     128
#define BN     128
#define KCH    64                 // K per chunk
#define KSPLIT 4
#define NCHU   (DIM / KCH / KSPLIT)   // 28 chunks per work unit
#define NSTAGE 3

#define TROW   144                // 64 fp16 = 128B + 16B pad (conflict-free ldmatrix)
#define TILEB  (128 * TROW)       // 18432 B
#define STAGEB (4 * TILEB)        // Ah Al Bh Bl = 73728 B
#define SMEMB  (NSTAGE * STAGEB)  // 221184 B

#define OFF_AH 0
#define OFF_AL TILEB
#define OFF_BH (2 * TILEB)
#define OFF_BL (3 * TILEB)

#define W_SCALE   64.0f
#define INV_SCALE 0.015625f

// Global scratch (allocation-free): pre-split fp16 operands + K-split partials.
__device__ __align__(16) __half g_xh[(size_t)NTOK * DIM];
__device__ __align__(16) __half g_xl[(size_t)NTOK * DIM];
__device__ __align__(16) __half g_wh[(size_t)NEXP * DIM];
__device__ __align__(16) __half g_wl[(size_t)NEXP * DIM];
__device__ __align__(16) float  g_part[(size_t)KSPLIT * NTOK * NEXP];  // 64 MB

// ---------------------------------------------------------------------------
// helpers
// ---------------------------------------------------------------------------
__device__ __forceinline__ uint32_t smem_u32(const void* p) {
    uint32_t a;
    asm("{ .reg .u64 t; cvta.to.shared.u64 t, %1; cvt.u32.u64 %0, t; }" : "=r"(a) : "l"(p));
    return a;
}

__device__ __forceinline__ void cp16(uint32_t dst, const void* src) {
    asm volatile("cp.async.cg.shared.global [%0], [%1], 16;" :: "r"(dst), "l"(src));
}
#define CP_COMMIT() asm volatile("cp.async.commit_group;" ::: "memory")
#define CP_WAIT1()  asm volatile("cp.async.wait_group 1;" ::: "memory")

#define LDMATRIX4(r, addr) \
    asm volatile("ldmatrix.sync.aligned.m8n8.x4.shared.b16 {%0,%1,%2,%3}, [%4];" \
        : "=r"((r)[0]), "=r"((r)[1]), "=r"((r)[2]), "=r"((r)[3]) : "r"(addr))

#define MMA16816F16(d, a, b0v, b1v) \
    asm volatile("mma.sync.aligned.m16n8k16.row.col.f32.f16.f16.f32 " \
        "{%0,%1,%2,%3}, {%4,%5,%6,%7}, {%8,%9}, {%0,%1,%2,%3};" \
        : "+f"((d)[0]), "+f"((d)[1]), "+f"((d)[2]), "+f"((d)[3]) \
        : "r"((a)[0]), "r"((a)[1]), "r"((a)[2]), "r"((a)[3]), "r"(b0v), "r"(b1v))

// Fast2Sum fold (exact PTX so the compiler can't simplify)
__device__ __forceinline__ void fast2sum(float& hi, float& lo) {
    float s, z;
    asm("add.rn.f32 %0, %1, %2;" : "=f"(s) : "f"(hi), "f"(lo));
    asm("sub.rn.f32 %0, %1, %2;" : "=f"(z) : "f"(s), "f"(hi));
    asm("sub.rn.f32 %0, %1, %2;" : "=f"(lo) : "f"(lo), "f"(z));
    hi = s;
}

// ---------------------------------------------------------------------------
// Prep: exact 2-way fp16 split of scaled fp32 stream.
// ---------------------------------------------------------------------------
__global__ void __launch_bounds__(256)
split_prep_kernel(const float* __restrict__ src,
                  __half* __restrict__ hO, __half* __restrict__ lO,
                  float scale, int n4)
{
    const float4* s4 = reinterpret_cast<const float4*>(src);
    int i = blockIdx.x * blockDim.x + threadIdx.x;
    const int stride = gridDim.x * blockDim.x;
    for (; i < n4; i += stride) {
        float4 v = s4[i];
        v.x *= scale; v.y *= scale; v.z *= scale; v.w *= scale;
        __half2 h0 = __floats2half2_rn(v.x, v.y);
        __half2 h1 = __floats2half2_rn(v.z, v.w);
        float2 f0 = __half22float2(h0), f1 = __half22float2(h1);
        __half2 l0 = __floats2half2_rn(v.x - f0.x, v.y - f0.y);
        __half2 l1 = __floats2half2_rn(v.z - f1.x, v.w - f1.y);
        uint2 hv, lv;
        hv.x = *reinterpret_cast<uint32_t*>(&h0);
        hv.y = *reinterpret_cast<uint32_t*>(&h1);
        lv.x = *reinterpret_cast<uint32_t*>(&l0);
        lv.y = *reinterpret_cast<uint32_t*>(&l1);
        *reinterpret_cast<uint2*>(hO + 4 * (size_t)i) = hv;
        *reinterpret_cast<uint2*>(lO + 4 * (size_t)i) = lv;
    }
}

// ---------------------------------------------------------------------------
// GEMM work unit: one (bm, bn) tile x one K-quarter (1792 K = 28 chunks).
// fp16 HMMA 3-pass (hh+hl+lh), cp.async 3-stage pipeline, Fast2Sum folds.
// 1024 equal units -> 1.2% wave-quantization idle (vs 15.6% at 256 CTAs).
// ---------------------------------------------------------------------------
extern __shared__ char dynsmem[];

__global__ void __launch_bounds__(256)
gemm_hmma_kernel()
{
    const int ksp  = blockIdx.x;     // 0..3  K-quarter (fast-varying)
    const int bn   = blockIdx.y;     // 0..1
    const int bm   = blockIdx.z;     // 0..127
    const int tid  = threadIdx.x;
    const int lane = tid & 31;
    const int wid  = tid >> 5;
    const int warp_m = wid >> 1;     // 0..3 -> token rows warp_m*32
    const int warp_n = wid & 1;      // 0..1 -> expert cols warp_n*64

    const uint32_t smem = smem_u32(dynsmem);

    const __half* xh_b = g_xh + (size_t)(bm * BM) * DIM;
    const __half* xl_b = g_xl + (size_t)(bm * BM) * DIM;
    const __half* wh_b = g_wh + (size_t)(bn * BN) * DIM;
    const __half* wl_b = g_wl + (size_t)(bn * BN) * DIM;
    const int kbase0 = ksp * NCHU * KCH;

    float acc[2][8][4];
    float hiv[2][8][4];
    #pragma unroll
    for (int a = 0; a < 2; a++)
        #pragma unroll
        for (int n = 0; n < 8; n++)
            #pragma unroll
            for (int r = 0; r < 4; r++) { acc[a][n][r] = 0.0f; hiv[a][n][r] = 0.0f; }

    // per-thread cp.async slots: q -> (row, 16B segment)
    auto issue_chunk = [&](int c) {
        const uint32_t sb = smem + (uint32_t)(c % NSTAGE) * STAGEB;
        const int kb = kbase0 + c * KCH;
        #pragma unroll
        for (int t = 0; t < 4; t++) {
            const int q = tid + t * 256;
            const int r = q >> 3;
            const int s = q & 7;
            const uint32_t d = sb + r * TROW + s * 16;
            const size_t go = (size_t)r * DIM + kb + s * 8;
            cp16(d + OFF_AH, xh_b + go);
            cp16(d + OFF_AL, xl_b + go);
            cp16(d + OFF_BH, wh_b + go);
            cp16(d + OFF_BL, wl_b + go);
        }
    };

    issue_chunk(0); CP_COMMIT();
    issue_chunk(1); CP_COMMIT();

    for (int c = 0; c < NCHU; ++c) {
        CP_WAIT1();                       // group for chunk c complete
        __syncthreads();                  // data visible; prior stage reads done

        if (c + 2 < NCHU) issue_chunk(c + 2);
        CP_COMMIT();                      // always commit (keeps group count in sync)

        const uint32_t stage = smem + (uint32_t)(c % NSTAGE) * STAGEB;

        #pragma unroll
        for (int ks = 0; ks < 4; ++ks) {
            uint32_t ah[2][4], al[2][4];
            #pragma unroll
            for (int amz = 0; amz < 2; ++amz) {
                const int row = warp_m * 32 + amz * 16 + (lane & 15);
                const int u   = ks * 2 + (lane >> 4);
                const uint32_t ad = stage + row * TROW + u * 16;
                LDMATRIX4(ah[amz], ad + OFF_AH);
                LDMATRIX4(al[amz], ad + OFF_AL);
            }
            #pragma unroll
            for (int pb = 0; pb < 4; pb += 2) {
                uint32_t bh2[2][4], bl2[2][4];
                #pragma unroll
                for (int pp = 0; pp < 2; ++pp) {
                    const int pair = pb + pp;
                    const int brow = warp_n * 64 + pair * 16 + (lane & 7) + ((lane >> 4) << 3);
                    const int u    = ks * 2 + ((lane >> 3) & 1);
                    const uint32_t bd = stage + brow * TROW + u * 16;
                    LDMATRIX4(bh2[pp], bd + OFF_BH);
                    LDMATRIX4(bl2[pp], bd + OFF_BL);
                }
                #pragma unroll
                for (int pp = 0; pp < 2; ++pp)
                    #pragma unroll
                    for (int amz = 0; amz < 2; ++amz)
                        #pragma unroll
                        for (int bo = 0; bo < 2; ++bo)
                            MMA16816F16(acc[amz][(pb + pp) * 2 + bo],
                                        ah[amz], bh2[pp][2*bo], bh2[pp][2*bo+1]);
                #pragma unroll
                for (int pp = 0; pp < 2; ++pp)
                    #pragma unroll
                    for (int amz = 0; amz < 2; ++amz)
                        #pragma unroll
                        for (int bo = 0; bo < 2; ++bo)
                            MMA16816F16(acc[amz][(pb + pp) * 2 + bo],
                                        ah[amz], bl2[pp][2*bo], bl2[pp][2*bo+1]);
                #pragma unroll
                for (int pp = 0; pp < 2; ++pp)
                    #pragma unroll
                    for (int amz = 0; amz < 2; ++amz)
                        #pragma unroll
                        for (int bo = 0; bo < 2; ++bo)
                            MMA16816F16(acc[amz][(pb + pp) * 2 + bo],
                                        al[amz], bh2[pp][2*bo], bh2[pp][2*bo+1]);
            }
        }

        if (c & 1) {
            #pragma unroll
            for (int a = 0; a < 2; a++)
                #pragma unroll
                for (int n = 0; n < 8; n++)
                    #pragma unroll
                    for (int r = 0; r < 4; r++)
                        fast2sum(hiv[a][n][r], acc[a][n][r]);
        }
    }

    // ---- write this K-quarter's partial (undo W scale) ----
    float* pout = g_part + (size_t)ksp * NTOK * NEXP;
    #pragma unroll
    for (int amz = 0; amz < 2; ++amz) {
        const int token = bm * BM + warp_m * 32 + amz * 16 + (lane >> 2);
        #pragma unroll
        for (int n = 0; n < 8; ++n) {
            const int expert = bn * BN + warp_n * 64 + n * 8 + (lane & 3) * 2;
            float d0 = (hiv[amz][n][0] + acc[amz][n][0]) * INV_SCALE;
            float d1 = (hiv[amz][n][1] + acc[amz][n][1]) * INV_SCALE;
            float d2 = (hiv[amz][n][2] + acc[amz][n][2]) * INV_SCALE;
            float d3 = (hiv[amz][n][3] + acc[amz][n][3]) * INV_SCALE;
            *reinterpret_cast<float2*>(&pout[(size_t)token * NEXP + expert]) =
                make_float2(d0, d1);
            *reinterpret_cast<float2*>(&pout[(size_t)(token + 8) * NEXP + expert]) =
                make_float2(d2, d3);
        }
    }
}

// ---------------------------------------------------------------------------
// Accurate exp (~2 ulp), immune to fast-math.
// ---------------------------------------------------------------------------
__device__ __forceinline__ float exp_acc(float xin) {
    float xc = fminf(fmaxf(xin, -30.0f), 30.0f);
    float k = rintf(xc * 1.4426950408889634f);
    float r = fmaf(k, -0.693359375f, xc);
    r = fmaf(k, 2.12194440054690e-4f, r);
    float p = 1.98412698e-4f;
    p = fmaf(p, r, 1.38888889e-3f);
    p = fmaf(p, r, 8.33333333e-3f);
    p = fmaf(p, r, 4.16666667e-2f);
    p = fmaf(p, r, 1.66666667e-1f);
    p = fmaf(p, r, 5.0e-1f);
    p = fmaf(p, r, 1.0f);
    p = fmaf(p, r, 1.0f);
    int ik = (int)k;
    float sc2 = __int_as_float((ik + 127) << 23);
    return p * sc2;
}

// ---------------------------------------------------------------------------
// Epilogue: WARP per token; sums the 4 K-split partials inline.
// ---------------------------------------------------------------------------
__global__ void __launch_bounds__(256)
gate_epilogue_warp(const float* __restrict__ bias,
                   float* __restrict__ out_w,
                   float* __restrict__ out_idx,
                   int write_idx)
{
    const unsigned FULL = 0xffffffffu;
    const int warp = threadIdx.x >> 5;
    const int lane = threadIdx.x & 31;
    const int t = blockIdx.x * 8 + warp;

    const size_t rowoff = (size_t)t * NEXP + lane * 8;
    const size_t PSTRIDE = (size_t)NTOK * NEXP;
    float4 a0 = *reinterpret_cast<const float4*>(g_part + rowoff);
    float4 a1 = *reinterpret_cast<const float4*>(g_part + rowoff + 4);
    float4 b0 = *reinterpret_cast<const float4*>(g_part + PSTRIDE + rowoff);
    float4 b1 = *reinterpret_cast<const float4*>(g_part + PSTRIDE + rowoff + 4);
    float4 c0 = *reinterpret_cast<const float4*>(g_part + 2 * PSTRIDE + rowoff);
    float4 c1 = *reinterpret_cast<const float4*>(g_part + 2 * PSTRIDE + rowoff + 4);
    float4 d0 = *reinterpret_cast<const float4*>(g_part + 3 * PSTRIDE + rowoff);
    float4 d1 = *reinterpret_cast<const float4*>(g_part + 3 * PSTRIDE + rowoff + 4);

    float lg[8];
    lg[0] = (a0.x + b0.x) + (c0.x + d0.x);
    lg[1] = (a0.y + b0.y) + (c0.y + d0.y);
    lg[2] = (a0.z + b0.z) + (c0.z + d0.z);
    lg[3] = (a0.w + b0.w) + (c0.w + d0.w);
    lg[4] = (a1.x + b1.x) + (c1.x + d1.x);
    lg[5] = (a1.y + b1.y) + (c1.y + d1.y);
    lg[6] = (a1.z + b1.z) + (c1.z + d1.z);
    lg[7] = (a1.w + b1.w) + (c1.w + d1.w);

    float4 bb0 = *reinterpret_cast<const float4*>(&bias[lane * 8]);
    float4 bb1 = *reinterpret_cast<const float4*>(&bias[lane * 8 + 4]);
    float bs[8] = {bb0.x, bb0.y, bb0.z, bb0.w, bb1.x, bb1.y, bb1.z, bb1.w};

    float sc[8], s[8];
    #pragma unroll
    for (int i = 0; i < 8; i++) {
        sc[i] = __fdiv_rn(1.0f, 1.0f + exp_acc(-lg[i]));
        s[i]  = sc[i] + bs[i];
    }

    // --- per-lane top-2 of 8, then merge across the 4-lane quad (one group) ---
    float v1 = -INFINITY, v2 = -INFINITY;
    #pragma unroll
    for (int i = 0; i < 8; i++) {
        if (s[i] > v1)      { v2 = v1; v1 = s[i]; }
        else if (s[i] > v2) { v2 = s[i]; }
    }
    #pragma unroll
    for (int o = 1; o <= 2; o <<= 1) {
        float u1 = __shfl_xor_sync(FULL, v1, o);
        float u2 = __shfl_xor_sync(FULL, v2, o);
        if (u1 > v1) { v2 = fmaxf(v1, u2); v1 = u1; }
        else         { v2 = fmaxf(v2, u1); }
    }
    const float gs = v1 + v2;       // all lanes of the quad agree

    // --- top-4 groups via rank (ties -> lower group index) ---
    float gv[8];
    #pragma unroll
    for (int g = 0; g < 8; g++) gv[g] = __shfl_sync(FULL, gs, g * 4);
    const int g0 = lane >> 2;
    int rank = 0;
    #pragma unroll
    for (int g = 0; g < 8; g++)
        rank += (gv[g] > gv[g0]) || (gv[g] == gv[g0] && g < g0);
    const bool keep = (rank < TOPG);

    float mv[8];
    #pragma unroll
    for (int i = 0; i < 8; i++) mv[i] = keep ? s[i] : -INFINITY;

    // --- masked top-8 (value desc, index asc) ---
    unsigned live = 0xffu;
    float rsc[8]; int ridx[8];
    float wsum = 0.0f;
    #pragma unroll
    for (int r = 0; r < TOPKN; r++) {
        float bv = -INFINITY, bsc2 = 0.0f;
        int bi = -1;
        #pragma unroll
        for (int i = 0; i < 8; i++) {
            if (((live >> i) & 1u) && mv[i] > bv) { bv = mv[i]; bsc2 = sc[i]; bi = i; }
        }
        int gidx = (bi >= 0) ? (lane * 8 + bi) : (1 << 30);
        float cv = bv, csc = bsc2;
        int ci = gidx;
        #pragma unroll
        for (int o = 16; o > 0; o >>= 1) {
            float ov  = __shfl_xor_sync(FULL, cv, o);
            int   oi  = __shfl_xor_sync(FULL, ci, o);
            float osc = __shfl_xor_sync(FULL, csc, o);
            if (ov > cv || (ov == cv && oi < ci)) { cv = ov; ci = oi; csc = osc; }
        }
        rsc[r] = csc; ridx[r] = ci;
        wsum += csc;
        if (lane == (ci >> 3)) live &= ~(1u << (ci & 7));
    }

    #pragma unroll
    for (int r = 0; r < TOPKN; r++) {
        if (lane == r) {
            out_w[(size_t)t * TOPKN + r] = __fdiv_rn(rsc[r], wsum) * 2.5f;
            if (write_idx) out_idx[(size_t)t * TOPKN + r] = (float)ridx[r];
        }
    }
}

// ---------------------------------------------------------------------------
extern "C" void kernel_launch(void* const* d_in, const int* in_sizes, int n_in,
                              void* d_out, int out_size)
{
    const float* x    = (const float*)d_in[0];   // [T, 7168]
    const float* w    = (const float*)d_in[1];   // [256, 7168]
    const float* bias = (const float*)d_in[2];   // [256]

    const int T = in_sizes[0] / DIM;             // 16384

    __half *p_xh, *p_xl, *p_wh, *p_wl;
    cudaGetSymbolAddress((void**)&p_xh, g_xh);
    cudaGetSymbolAddress((void**)&p_xl, g_xl);
    cudaGetSymbolAddress((void**)&p_wh, g_wh);
    cudaGetSymbolAddress((void**)&p_wl, g_wl);

    split_prep_kernel<<<4096, 256>>>(x, p_xh, p_xl, 1.0f, T * DIM / 4);
    split_prep_kernel<<<256, 256>>>(w, p_wh, p_wl, W_SCALE, NEXP * DIM / 4);

    cudaFuncSetAttribute(gemm_hmma_kernel,
                         cudaFuncAttributeMaxDynamicSharedMemorySize, SMEMB);

    dim3 grid(KSPLIT, NEXP / BN, T / BM);        // (4, 2, 128): 1024 equal units
    gemm_hmma_kernel<<<grid, 256, SMEMB>>>();

    float* out = (float*)d_out;
    const int write_idx = (out_size >= 2 * T * TOPKN) ? 1 : 0;
    gate_epilogue_warp<<<T / 8, 256>>>(bias, out, out + (size_t)T * TOPKN, write_idx);
}

// round 11
// speedup vs baseline: 1.3211x; 1.0254x over previous
#include <cuda_runtime.h>
#include <cuda_fp16.h>
#include <cstdint>
#include <math.h>

#define DIM    7168
#define NEXP   256
#define NTOK   16384
#define TOPKN  8
#define NGRP   8
#define TOPG   4

#define BM     128
#define BN     128
#define KCH    64                 // K per chunk
#define KSPLIT 4
#define NCHU   (DIM / KCH / KSPLIT)   // 28 chunks per work unit
#define NSTAGE 3

#define TROW   144                // 64 fp16 = 128B + 16B pad (conflict-free ldmatrix)
#define TILEB  (128 * TROW)       // 18432 B
#define STAGEB (4 * TILEB)        // Ah Al Bh Bl = 73728 B
#define SMEMB  (NSTAGE * STAGEB)  // 221184 B

#define OFF_AH 0
#define OFF_AL TILEB
#define OFF_BH (2 * TILEB)
#define OFF_BL (3 * TILEB)

#define W_SCALE   64.0f
#define INV_SCALE 0.015625f

// Global scratch (allocation-free): pre-split fp16 w + K-split partials.
// (x is split in-GEMM now: raw fp32 x read = same bytes as fp16 xh+xl.)
__device__ __align__(16) __half g_wh[(size_t)NEXP * DIM];
__device__ __align__(16) __half g_wl[(size_t)NEXP * DIM];
__device__ __align__(16) float  g_part[(size_t)KSPLIT * NTOK * NEXP];  // 64 MB

// ---------------------------------------------------------------------------
// helpers
// ---------------------------------------------------------------------------
__device__ __forceinline__ uint32_t smem_u32(const void* p) {
    uint32_t a;
    asm("{ .reg .u64 t; cvta.to.shared.u64 t, %1; cvt.u32.u64 %0, t; }" : "=r"(a) : "l"(p));
    return a;
}

__device__ __forceinline__ void cp16(uint32_t dst, const void* src) {
    asm volatile("cp.async.cg.shared.global [%0], [%1], 16;" :: "r"(dst), "l"(src));
}
#define CP_COMMIT() asm volatile("cp.async.commit_group;" ::: "memory")
#define CP_WAIT1()  asm volatile("cp.async.wait_group 1;" ::: "memory")

#define LDMATRIX4(r, addr) \
    asm volatile("ldmatrix.sync.aligned.m8n8.x4.shared.b16 {%0,%1,%2,%3}, [%4];" \
        : "=r"((r)[0]), "=r"((r)[1]), "=r"((r)[2]), "=r"((r)[3]) : "r"(addr))

#define MMA16816F16(d, a, b0v, b1v) \
    asm volatile("mma.sync.aligned.m16n8k16.row.col.f32.f16.f16.f32 " \
        "{%0,%1,%2,%3}, {%4,%5,%6,%7}, {%8,%9}, {%0,%1,%2,%3};" \
        : "+f"((d)[0]), "+f"((d)[1]), "+f"((d)[2]), "+f"((d)[3]) \
        : "r"((a)[0]), "r"((a)[1]), "r"((a)[2]), "r"((a)[3]), "r"(b0v), "r"(b1v))

// Fast2Sum fold (exact PTX so the compiler can't simplify)
__device__ __forceinline__ void fast2sum(float& hi, float& lo) {
    float s, z;
    asm("add.rn.f32 %0, %1, %2;" : "=f"(s) : "f"(hi), "f"(lo));
    asm("sub.rn.f32 %0, %1, %2;" : "=f"(z) : "f"(s), "f"(hi));
    asm("sub.rn.f32 %0, %1, %2;" : "=f"(lo) : "f"(lo), "f"(z));
    hi = s;
}

// 2-way fp16 split of 2 fp32 -> two f16x2 (elem0 in low 16). Same rounding
// ops as the previous prep kernel: h = rn(v), l = rn(v - h).
__device__ __forceinline__ void splitf16_2(float e0, float e1, uint32_t& H, uint32_t& L) {
    __half2 h = __floats2half2_rn(e0, e1);
    float2 hf = __half22float2(h);
    __half2 l = __floats2half2_rn(e0 - hf.x, e1 - hf.y);
    H = *reinterpret_cast<uint32_t*>(&h);
    L = *reinterpret_cast<uint32_t*>(&l);
}
__device__ __forceinline__ void split8(float4 v0, float4 v1, uint4& H, uint4& L) {
    splitf16_2(v0.x, v0.y, H.x, L.x);
    splitf16_2(v0.z, v0.w, H.y, L.y);
    splitf16_2(v1.x, v1.y, H.z, L.z);
    splitf16_2(v1.z, v1.w, H.w, L.w);
}

// ---------------------------------------------------------------------------
// Prep (w only): exact 2-way fp16 split of scaled fp32 stream. ~7 MB, ~5us.
// ---------------------------------------------------------------------------
__global__ void __launch_bounds__(256)
split_prep_kernel(const float* __restrict__ src,
                  __half* __restrict__ hO, __half* __restrict__ lO,
                  float scale, int n4)
{
    const float4* s4 = reinterpret_cast<const float4*>(src);
    int i = blockIdx.x * blockDim.x + threadIdx.x;
    const int stride = gridDim.x * blockDim.x;
    for (; i < n4; i += stride) {
        float4 v = s4[i];
        v.x *= scale; v.y *= scale; v.z *= scale; v.w *= scale;
        __half2 h0 = __floats2half2_rn(v.x, v.y);
        __half2 h1 = __floats2half2_rn(v.z, v.w);
        float2 f0 = __half22float2(h0), f1 = __half22float2(h1);
        __half2 l0 = __floats2half2_rn(v.x - f0.x, v.y - f0.y);
        __half2 l1 = __floats2half2_rn(v.z - f1.x, v.w - f1.y);
        uint2 hv, lv;
        hv.x = *reinterpret_cast<uint32_t*>(&h0);
        hv.y = *reinterpret_cast<uint32_t*>(&h1);
        lv.x = *reinterpret_cast<uint32_t*>(&l0);
        lv.y = *reinterpret_cast<uint32_t*>(&l1);
        *reinterpret_cast<uint2*>(hO + 4 * (size_t)i) = hv;
        *reinterpret_cast<uint2*>(lO + 4 * (size_t)i) = lv;
    }
}

// ---------------------------------------------------------------------------
// GEMM work unit: one (bm, bn) tile x one K-quarter (28 chunks).
// fp16 HMMA 3-pass (hh+hl+lh); B via cp.async 3-stage pipeline on pre-split w;
// A loaded as raw fp32 x, split in-kernel (hidden under mma), STS'd into the
// same pipeline stage. Single barrier per chunk. Fast2Sum folds.
// ---------------------------------------------------------------------------
extern __shared__ char dynsmem[];

__global__ void __launch_bounds__(256)
gemm_hmma_kernel(const float* __restrict__ x)
{
    const int ksp  = blockIdx.x;     // 0..3  K-quarter
    const int bn   = blockIdx.y;     // 0..1
    const int bm   = blockIdx.z;     // 0..127
    const int tid  = threadIdx.x;
    const int lane = tid & 31;
    const int wid  = tid >> 5;
    const int warp_m = wid >> 1;     // 0..3 -> token rows warp_m*32
    const int warp_n = wid & 1;      // 0..1 -> expert cols warp_n*64

    const uint32_t smem = smem_u32(dynsmem);

    const float*  x_b  = x + (size_t)(bm * BM) * DIM;
    const __half* wh_b = g_wh + (size_t)(bn * BN) * DIM;
    const __half* wl_b = g_wl + (size_t)(bn * BN) * DIM;
    const int kbase0 = ksp * NCHU * KCH;

    // A loader mapping: thread owns row arow, 32-col half ahalf of each chunk
    const int arow  = tid >> 1;      // 0..127
    const int ahalf = tid & 1;       // 0..1

    float acc[2][8][4];
    float hiv[2][8][4];
    #pragma unroll
    for (int a = 0; a < 2; a++)
        #pragma unroll
        for (int n = 0; n < 8; n++)
            #pragma unroll
            for (int r = 0; r < 4; r++) { acc[a][n][r] = 0.0f; hiv[a][n][r] = 0.0f; }

    float4 pf[8];   // 32 fp32 of next chunk's A

    auto ldgA = [&](int c) {
        const float* src = x_b + (size_t)arow * DIM + kbase0 + c * KCH + ahalf * 32;
        #pragma unroll
        for (int q = 0; q < 8; q++) pf[q] = *reinterpret_cast<const float4*>(src + q * 4);
    };
    auto splitStsA = [&](int c) {
        char* sb = dynsmem + (size_t)(c % NSTAGE) * STAGEB;
        const int off = arow * TROW + ahalf * 64;
        #pragma unroll
        for (int j = 0; j < 4; j++) {
            uint4 H, L;
            split8(pf[2 * j], pf[2 * j + 1], H, L);
            *reinterpret_cast<uint4*>(sb + OFF_AH + off + j * 16) = H;
            *reinterpret_cast<uint4*>(sb + OFF_AL + off + j * 16) = L;
        }
    };
    auto issueB = [&](int c) {
        const uint32_t sb = smem + (uint32_t)(c % NSTAGE) * STAGEB;
        const int kb = kbase0 + c * KCH;
        #pragma unroll
        for (int t = 0; t < 4; t++) {
            const int q = tid + t * 256;
            const int r = q >> 3;
            const int s = q & 7;
            const uint32_t d = sb + r * TROW + s * 16;
            const size_t go = (size_t)r * DIM + kb + s * 8;
            cp16(d + OFF_BH, wh_b + go);
            cp16(d + OFF_BL, wl_b + go);
        }
    };

    // prologue: A(0) split+STS (visible after first barrier); B(0), B(1) in flight
    ldgA(0); splitStsA(0);
    issueB(0); CP_COMMIT();
    issueB(1); CP_COMMIT();

    for (int c = 0; c < NCHU; ++c) {
        CP_WAIT1();                       // B(c) complete
        __syncthreads();                  // B(c) + STS A(c) visible; old-stage reads done

        if (c + 2 < NCHU) issueB(c + 2);
        CP_COMMIT();                      // keep group count in sync
        if (c + 1 < NCHU) ldgA(c + 1);    // LDG early; hidden under mma

        const uint32_t stage = smem + (uint32_t)(c % NSTAGE) * STAGEB;

        #pragma unroll
        for (int ks = 0; ks < 4; ++ks) {
            uint32_t ah[2][4], al[2][4];
            #pragma unroll
            for (int amz = 0; amz < 2; ++amz) {
                const int row = warp_m * 32 + amz * 16 + (lane & 15);
                const int u   = ks * 2 + (lane >> 4);
                const uint32_t ad = stage + row * TROW + u * 16;
                LDMATRIX4(ah[amz], ad + OFF_AH);
                LDMATRIX4(al[amz], ad + OFF_AL);
            }
            #pragma unroll
            for (int pb = 0; pb < 4; pb += 2) {
                uint32_t bh2[2][4], bl2[2][4];
                #pragma unroll
                for (int pp = 0; pp < 2; ++pp) {
                    const int pair = pb + pp;
                    const int brow = warp_n * 64 + pair * 16 + (lane & 7) + ((lane >> 4) << 3);
                    const int u    = ks * 2 + ((lane >> 3) & 1);
                    const uint32_t bd = stage + brow * TROW + u * 16;
                    LDMATRIX4(bh2[pp], bd + OFF_BH);
                    LDMATRIX4(bl2[pp], bd + OFF_BL);
                }
                #pragma unroll
                for (int pp = 0; pp < 2; ++pp)
                    #pragma unroll
                    for (int amz = 0; amz < 2; ++amz)
                        #pragma unroll
                        for (int bo = 0; bo < 2; ++bo)
                            MMA16816F16(acc[amz][(pb + pp) * 2 + bo],
                                        ah[amz], bh2[pp][2*bo], bh2[pp][2*bo+1]);
                #pragma unroll
                for (int pp = 0; pp < 2; ++pp)
                    #pragma unroll
                    for (int amz = 0; amz < 2; ++amz)
                        #pragma unroll
                        for (int bo = 0; bo < 2; ++bo)
                            MMA16816F16(acc[amz][(pb + pp) * 2 + bo],
                                        ah[amz], bl2[pp][2*bo], bl2[pp][2*bo+1]);
                #pragma unroll
                for (int pp = 0; pp < 2; ++pp)
                    #pragma unroll
                    for (int amz = 0; amz < 2; ++amz)
                        #pragma unroll
                        for (int bo = 0; bo < 2; ++bo)
                            MMA16816F16(acc[amz][(pb + pp) * 2 + bo],
                                        al[amz], bh2[pp][2*bo], bh2[pp][2*bo+1]);
            }
        }

        if (c + 1 < NCHU) splitStsA(c + 1);   // into stage (c+1)%3: free since mma(c-2)

        if (c & 1) {
            #pragma unroll
            for (int a = 0; a < 2; a++)
                #pragma unroll
                for (int n = 0; n < 8; n++)
                    #pragma unroll
                    for (int r = 0; r < 4; r++)
                        fast2sum(hiv[a][n][r], acc[a][n][r]);
        }
    }

    // ---- write this K-quarter's partial (undo W scale) ----
    float* pout = g_part + (size_t)ksp * NTOK * NEXP;
    #pragma unroll
    for (int amz = 0; amz < 2; ++amz) {
        const int token = bm * BM + warp_m * 32 + amz * 16 + (lane >> 2);
        #pragma unroll
        for (int n = 0; n < 8; ++n) {
            const int expert = bn * BN + warp_n * 64 + n * 8 + (lane & 3) * 2;
            float d0 = (hiv[amz][n][0] + acc[amz][n][0]) * INV_SCALE;
            float d1 = (hiv[amz][n][1] + acc[amz][n][1]) * INV_SCALE;
            float d2 = (hiv[amz][n][2] + acc[amz][n][2]) * INV_SCALE;
            float d3 = (hiv[amz][n][3] + acc[amz][n][3]) * INV_SCALE;
            *reinterpret_cast<float2*>(&pout[(size_t)token * NEXP + expert]) =
                make_float2(d0, d1);
            *reinterpret_cast<float2*>(&pout[(size_t)(token + 8) * NEXP + expert]) =
                make_float2(d2, d3);
        }
    }
}

// ---------------------------------------------------------------------------
// Accurate exp (~2 ulp), immune to fast-math.
// ---------------------------------------------------------------------------
__device__ __forceinline__ float exp_acc(float xin) {
    float xc = fminf(fmaxf(xin, -30.0f), 30.0f);
    float k = rintf(xc * 1.4426950408889634f);
    float r = fmaf(k, -0.693359375f, xc);
    r = fmaf(k, 2.12194440054690e-4f, r);
    float p = 1.98412698e-4f;
    p = fmaf(p, r, 1.38888889e-3f);
    p = fmaf(p, r, 8.33333333e-3f);
    p = fmaf(p, r, 4.16666667e-2f);
    p = fmaf(p, r, 1.66666667e-1f);
    p = fmaf(p, r, 5.0e-1f);
    p = fmaf(p, r, 1.0f);
    p = fmaf(p, r, 1.0f);
    int ik = (int)k;
    float sc2 = __int_as_float((ik + 127) << 23);
    return p * sc2;
}

// ---------------------------------------------------------------------------
// Epilogue: WARP per token; sums the 4 K-split partials inline.
// ---------------------------------------------------------------------------
__global__ void __launch_bounds__(256)
gate_epilogue_warp(const float* __restrict__ bias,
                   float* __restrict__ out_w,
                   float* __restrict__ out_idx,
                   int write_idx)
{
    const unsigned FULL = 0xffffffffu;
    const int warp = threadIdx.x >> 5;
    const int lane = threadIdx.x & 31;
    const int t = blockIdx.x * 8 + warp;

    const size_t rowoff = (size_t)t * NEXP + lane * 8;
    const size_t PSTRIDE = (size_t)NTOK * NEXP;
    float4 a0 = *reinterpret_cast<const float4*>(g_part + rowoff);
    float4 a1 = *reinterpret_cast<const float4*>(g_part + rowoff + 4);
    float4 b0 = *reinterpret_cast<const float4*>(g_part + PSTRIDE + rowoff);
    float4 b1 = *reinterpret_cast<const float4*>(g_part + PSTRIDE + rowoff + 4);
    float4 c0 = *reinterpret_cast<const float4*>(g_part + 2 * PSTRIDE + rowoff);
    float4 c1 = *reinterpret_cast<const float4*>(g_part + 2 * PSTRIDE + rowoff + 4);
    float4 d0 = *reinterpret_cast<const float4*>(g_part + 3 * PSTRIDE + rowoff);
    float4 d1 = *reinterpret_cast<const float4*>(g_part + 3 * PSTRIDE + rowoff + 4);

    float lg[8];
    lg[0] = (a0.x + b0.x) + (c0.x + d0.x);
    lg[1] = (a0.y + b0.y) + (c0.y + d0.y);
    lg[2] = (a0.z + b0.z) + (c0.z + d0.z);
    lg[3] = (a0.w + b0.w) + (c0.w + d0.w);
    lg[4] = (a1.x + b1.x) + (c1.x + d1.x);
    lg[5] = (a1.y + b1.y) + (c1.y + d1.y);
    lg[6] = (a1.z + b1.z) + (c1.z + d1.z);
    lg[7] = (a1.w + b1.w) + (c1.w + d1.w);

    float4 bb0 = *reinterpret_cast<const float4*>(&bias[lane * 8]);
    float4 bb1 = *reinterpret_cast<const float4*>(&bias[lane * 8 + 4]);
    float bs[8] = {bb0.x, bb0.y, bb0.z, bb0.w, bb1.x, bb1.y, bb1.z, bb1.w};

    float sc[8], s[8];
    #pragma unroll
    for (int i = 0; i < 8; i++) {
        sc[i] = __fdiv_rn(1.0f, 1.0f + exp_acc(-lg[i]));
        s[i]  = sc[i] + bs[i];
    }

    // --- per-lane top-2 of 8, then merge across the 4-lane quad (one group) ---
    float v1 = -INFINITY, v2 = -INFINITY;
    #pragma unroll
    for (int i = 0; i < 8; i++) {
        if (s[i] > v1)      { v2 = v1; v1 = s[i]; }
        else if (s[i] > v2) { v2 = s[i]; }
    }
    #pragma unroll
    for (int o = 1; o <= 2; o <<= 1) {
        float u1 = __shfl_xor_sync(FULL, v1, o);
        float u2 = __shfl_xor_sync(FULL, v2, o);
        if (u1 > v1) { v2 = fmaxf(v1, u2); v1 = u1; }
        else         { v2 = fmaxf(v2, u1); }
    }
    const float gs = v1 + v2;       // all lanes of the quad agree

    // --- top-4 groups via rank (ties -> lower group index) ---
    float gv[8];
    #pragma unroll
    for (int g = 0; g < 8; g++) gv[g] = __shfl_sync(FULL, gs, g * 4);
    const int g0 = lane >> 2;
    int rank = 0;
    #pragma unroll
    for (int g = 0; g < 8; g++)
        rank += (gv[g] > gv[g0]) || (gv[g] == gv[g0] && g < g0);
    const bool keep = (rank < TOPG);

    float mv[8];
    #pragma unroll
    for (int i = 0; i < 8; i++) mv[i] = keep ? s[i] : -INFINITY;

    // --- masked top-8 (value desc, index asc) ---
    unsigned live = 0xffu;
    float rsc[8]; int ridx[8];
    float wsum = 0.0f;
    #pragma unroll
    for (int r = 0; r < TOPKN; r++) {
        float bv = -INFINITY, bsc2 = 0.0f;
        int bi = -1;
        #pragma unroll
        for (int i = 0; i < 8; i++) {
            if (((live >> i) & 1u) && mv[i] > bv) { bv = mv[i]; bsc2 = sc[i]; bi = i; }
        }
        int gidx = (bi >= 0) ? (lane * 8 + bi) : (1 << 30);
        float cv = bv, csc = bsc2;
        int ci = gidx;
        #pragma unroll
        for (int o = 16; o > 0; o >>= 1) {
            float ov  = __shfl_xor_sync(FULL, cv, o);
            int   oi  = __shfl_xor_sync(FULL, ci, o);
            float osc = __shfl_xor_sync(FULL, csc, o);
            if (ov > cv || (ov == cv && oi < ci)) { cv = ov; ci = oi; csc = osc; }
        }
        rsc[r] = csc; ridx[r] = ci;
        wsum += csc;
        if (lane == (ci >> 3)) live &= ~(1u << (ci & 7));
    }

    #pragma unroll
    for (int r = 0; r < TOPKN; r++) {
        if (lane == r) {
            out_w[(size_t)t * TOPKN + r] = __fdiv_rn(rsc[r], wsum) * 2.5f;
            if (write_idx) out_idx[(size_t)t * TOPKN + r] = (float)ridx[r];
        }
    }
}

// ---------------------------------------------------------------------------
extern "C" void kernel_launch(void* const* d_in, const int* in_sizes, int n_in,
                              void* d_out, int out_size)
{
    const float* x    = (const float*)d_in[0];   // [T, 7168]
    const float* w    = (const float*)d_in[1];   // [256, 7168]
    const float* bias = (const float*)d_in[2];   // [256]

    const int T = in_sizes[0] / DIM;             // 16384

    __half *p_wh, *p_wl;
    cudaGetSymbolAddress((void**)&p_wh, g_wh);
    cudaGetSymbolAddress((void**)&p_wl, g_wl);

    // w only: 7.3 MB, ~5 us
    split_prep_kernel<<<256, 256>>>(w, p_wh, p_wl, W_SCALE, NEXP * DIM / 4);

    cudaFuncSetAttribute(gemm_hmma_kernel,
                         cudaFuncAttributeMaxDynamicSharedMemorySize, SMEMB);

    dim3 grid(KSPLIT, NEXP / BN, T / BM);        // (4, 2, 128): 1024 equal units
    gemm_hmma_kernel<<<grid, 256, SMEMB>>>(x);

    float* out = (float*)d_out;
    const int write_idx = (out_size >= 2 * T * TOPKN) ? 1 : 0;
    gate_epilogue_warp<<<T / 8, 256>>>(bias, out, out + (size_t)T * TOPKN, write_idx);
}

// round 12
// speedup vs baseline: 1.4707x; 1.1132x over previous
#include <cuda_runtime.h>
#include <cuda_fp16.h>
#include <cstdint>
#include <math.h>

#define DIM    7168
#define NEXP   256
#define NTOK   16384
#define TOPKN  8
#define NGRP   8
#define TOPG   4

#define BM     128
#define BN     128
#define KCH    64                 // K per chunk
#define KSPLIT 4
#define NCHU   (DIM / KCH / KSPLIT)   // 28 chunks per work unit
#define NSTAGE 3

#define TROW   144                // 64 fp16 = 128B + 16B pad (conflict-free ldmatrix)
#define TILEB  (128 * TROW)       // 18432 B
#define STAGEB (4 * TILEB)        // Ah Al Bh Bl = 73728 B
#define SMEMB  (NSTAGE * STAGEB)  // 221184 B

#define OFF_AH 0
#define OFF_AL TILEB
#define OFF_BH (2 * TILEB)
#define OFF_BL (3 * TILEB)

#define W_SCALE   64.0f
#define INV_SCALE 0.015625f

// Global scratch (allocation-free): pre-split fp16 w + K-split partials.
__device__ __align__(16) __half g_wh[(size_t)NEXP * DIM];
__device__ __align__(16) __half g_wl[(size_t)NEXP * DIM];
__device__ __align__(16) float  g_part[(size_t)KSPLIT * NTOK * NEXP];  // 64 MB

// ---------------------------------------------------------------------------
// helpers
// ---------------------------------------------------------------------------
__device__ __forceinline__ uint32_t smem_u32(const void* p) {
    uint32_t a;
    asm("{ .reg .u64 t; cvta.to.shared.u64 t, %1; cvt.u32.u64 %0, t; }" : "=r"(a) : "l"(p));
    return a;
}

__device__ __forceinline__ void cp16(uint32_t dst, const void* src) {
    asm volatile("cp.async.cg.shared.global [%0], [%1], 16;" :: "r"(dst), "l"(src));
}
#define CP_COMMIT() asm volatile("cp.async.commit_group;" ::: "memory")
#define CP_WAIT1()  asm volatile("cp.async.wait_group 1;" ::: "memory")

#define LDMATRIX4(r, addr) \
    asm volatile("ldmatrix.sync.aligned.m8n8.x4.shared.b16 {%0,%1,%2,%3}, [%4];" \
        : "=r"((r)[0]), "=r"((r)[1]), "=r"((r)[2]), "=r"((r)[3]) : "r"(addr))

#define MMA16816F16(d, a, b0v, b1v) \
    asm volatile("mma.sync.aligned.m16n8k16.row.col.f32.f16.f16.f32 " \
        "{%0,%1,%2,%3}, {%4,%5,%6,%7}, {%8,%9}, {%0,%1,%2,%3};" \
        : "+f"((d)[0]), "+f"((d)[1]), "+f"((d)[2]), "+f"((d)[3]) \
        : "r"((a)[0]), "r"((a)[1]), "r"((a)[2]), "r"((a)[3]), "r"(b0v), "r"(b1v))

// Fast2Sum fold (exact PTX so the compiler can't simplify)
__device__ __forceinline__ void fast2sum(float& hi, float& lo) {
    float s, z;
    asm("add.rn.f32 %0, %1, %2;" : "=f"(s) : "f"(hi), "f"(lo));
    asm("sub.rn.f32 %0, %1, %2;" : "=f"(z) : "f"(s), "f"(hi));
    asm("sub.rn.f32 %0, %1, %2;" : "=f"(lo) : "f"(lo), "f"(z));
    hi = s;
}

// 2-way fp16 split of 2 fp32 -> two f16x2 (elem0 in low 16). Same rounding
// ops as the prep kernel: h = rn(v), l = rn(v - h).
__device__ __forceinline__ void splitf16_2(float e0, float e1, uint32_t& H, uint32_t& L) {
    __half2 h = __floats2half2_rn(e0, e1);
    float2 hf = __half22float2(h);
    __half2 l = __floats2half2_rn(e0 - hf.x, e1 - hf.y);
    H = *reinterpret_cast<uint32_t*>(&h);
    L = *reinterpret_cast<uint32_t*>(&l);
}
__device__ __forceinline__ void split8(float4 v0, float4 v1, uint4& H, uint4& L) {
    splitf16_2(v0.x, v0.y, H.x, L.x);
    splitf16_2(v0.z, v0.w, H.y, L.y);
    splitf16_2(v1.x, v1.y, H.z, L.z);
    splitf16_2(v1.z, v1.w, H.w, L.w);
}

// ---------------------------------------------------------------------------
// Prep (w only): exact 2-way fp16 split of scaled fp32 stream. ~7 MB, ~8us.
// ---------------------------------------------------------------------------
__global__ void __launch_bounds__(256)
split_prep_kernel(const float* __restrict__ src,
                  __half* __restrict__ hO, __half* __restrict__ lO,
                  float scale, int n4)
{
    const float4* s4 = reinterpret_cast<const float4*>(src);
    int i = blockIdx.x * blockDim.x + threadIdx.x;
    const int stride = gridDim.x * blockDim.x;
    for (; i < n4; i += stride) {
        float4 v = s4[i];
        v.x *= scale; v.y *= scale; v.z *= scale; v.w *= scale;
        __half2 h0 = __floats2half2_rn(v.x, v.y);
        __half2 h1 = __floats2half2_rn(v.z, v.w);
        float2 f0 = __half22float2(h0), f1 = __half22float2(h1);
        __half2 l0 = __floats2half2_rn(v.x - f0.x, v.y - f0.y);
        __half2 l1 = __floats2half2_rn(v.z - f1.x, v.w - f1.y);
        uint2 hv, lv;
        hv.x = *reinterpret_cast<uint32_t*>(&h0);
        hv.y = *reinterpret_cast<uint32_t*>(&h1);
        lv.x = *reinterpret_cast<uint32_t*>(&l0);
        lv.y = *reinterpret_cast<uint32_t*>(&l1);
        *reinterpret_cast<uint2*>(hO + 4 * (size_t)i) = hv;
        *reinterpret_cast<uint2*>(lO + 4 * (size_t)i) = lv;
    }
}

// ---------------------------------------------------------------------------
// GEMM work unit: one (bm, bn) tile x one K-quarter (28 chunks).
// fp16 HMMA 3-pass (hh+hl+lh); B via cp.async 3-stage pipeline on pre-split w;
// A loaded as raw fp32 x with COALESCED mapping (8 threads sweep one row),
// split in-kernel mid-MMA-loop, STS'd into the same pipeline stage.
// Single barrier per chunk. Fast2Sum folds.
// ---------------------------------------------------------------------------
extern __shared__ char dynsmem[];

__global__ void __launch_bounds__(256)
gemm_hmma_kernel(const float* __restrict__ x)
{
    const int ksp  = blockIdx.x;     // 0..3  K-quarter
    const int bn   = blockIdx.y;     // 0..1
    const int bm   = blockIdx.z;     // 0..127
    const int tid  = threadIdx.x;
    const int lane = tid & 31;
    const int wid  = tid >> 5;
    const int warp_m = wid >> 1;     // 0..3 -> token rows warp_m*32
    const int warp_n = wid & 1;      // 0..1 -> expert cols warp_n*64

    const uint32_t smem = smem_u32(dynsmem);

    const float*  x_b  = x + (size_t)(bm * BM) * DIM;
    const __half* wh_b = g_wh + (size_t)(bn * BN) * DIM;
    const __half* wl_b = g_wl + (size_t)(bn * BN) * DIM;
    const int kbase0 = ksp * NCHU * KCH;

    // A loader: iteration 'it' covers rows (tid>>3)+32*it; thread owns 8
    // contiguous floats at col (tid&7)*8.  8 consecutive threads sweep one
    // 256B row -> 8 lines per LDG warp-request (coalesced).
    const int arow0 = tid >> 3;      // 0..31
    const int aseg  = tid & 7;       // 0..7  (8 floats each)

    float acc[2][8][4];
    float hiv[2][8][4];
    #pragma unroll
    for (int a = 0; a < 2; a++)
        #pragma unroll
        for (int n = 0; n < 8; n++)
            #pragma unroll
            for (int r = 0; r < 4; r++) { acc[a][n][r] = 0.0f; hiv[a][n][r] = 0.0f; }

    float4 pf[8];   // 4 iterations x 2 float4 = 32 fp32 of next chunk's A

    auto ldgA = [&](int c) {
        const int kb = kbase0 + c * KCH;
        #pragma unroll
        for (int it = 0; it < 4; ++it) {
            const float* src = x_b + (size_t)(arow0 + it * 32) * DIM + kb + aseg * 8;
            pf[it * 2]     = *reinterpret_cast<const float4*>(src);
            pf[it * 2 + 1] = *reinterpret_cast<const float4*>(src + 4);
        }
    };
    auto splitStsA = [&](int c) {
        char* sb = dynsmem + (size_t)(c % NSTAGE) * STAGEB;
        #pragma unroll
        for (int it = 0; it < 4; ++it) {
            const int off = (arow0 + it * 32) * TROW + aseg * 16;
            uint4 H, L;
            split8(pf[it * 2], pf[it * 2 + 1], H, L);
            *reinterpret_cast<uint4*>(sb + OFF_AH + off) = H;
            *reinterpret_cast<uint4*>(sb + OFF_AL + off) = L;
        }
    };
    auto issueB = [&](int c) {
        const uint32_t sb = smem + (uint32_t)(c % NSTAGE) * STAGEB;
        const int kb = kbase0 + c * KCH;
        #pragma unroll
        for (int t = 0; t < 4; t++) {
            const int q = tid + t * 256;
            const int r = q >> 3;
            const int s = q & 7;
            const uint32_t d = sb + r * TROW + s * 16;
            const size_t go = (size_t)r * DIM + kb + s * 8;
            cp16(d + OFF_BH, wh_b + go);
            cp16(d + OFF_BL, wl_b + go);
        }
    };

    // prologue: A(0) split+STS (visible after first barrier); B(0), B(1) in flight
    ldgA(0); splitStsA(0);
    issueB(0); CP_COMMIT();
    issueB(1); CP_COMMIT();

    for (int c = 0; c < NCHU; ++c) {
        CP_WAIT1();                       // B(c) complete
        __syncthreads();                  // B(c) + STS A(c) visible; old-stage reads done

        if (c + 2 < NCHU) issueB(c + 2);
        CP_COMMIT();                      // keep group count in sync
        if (c + 1 < NCHU) ldgA(c + 1);    // LDG early; covered by ks=0,1 mma

        const uint32_t stage = smem + (uint32_t)(c % NSTAGE) * STAGEB;

        #pragma unroll
        for (int ks = 0; ks < 4; ++ks) {
            uint32_t ah[2][4], al[2][4];
            #pragma unroll
            for (int amz = 0; amz < 2; ++amz) {
                const int row = warp_m * 32 + amz * 16 + (lane & 15);
                const int u   = ks * 2 + (lane >> 4);
                const uint32_t ad = stage + row * TROW + u * 16;
                LDMATRIX4(ah[amz], ad + OFF_AH);
                LDMATRIX4(al[amz], ad + OFF_AL);
            }
            #pragma unroll
            for (int pb = 0; pb < 4; pb += 2) {
                uint32_t bh2[2][4], bl2[2][4];
                #pragma unroll
                for (int pp = 0; pp < 2; ++pp) {
                    const int pair = pb + pp;
                    const int brow = warp_n * 64 + pair * 16 + (lane & 7) + ((lane >> 4) << 3);
                    const int u    = ks * 2 + ((lane >> 3) & 1);
                    const uint32_t bd = stage + brow * TROW + u * 16;
                    LDMATRIX4(bh2[pp], bd + OFF_BH);
                    LDMATRIX4(bl2[pp], bd + OFF_BL);
                }
                #pragma unroll
                for (int pp = 0; pp < 2; ++pp)
                    #pragma unroll
                    for (int amz = 0; amz < 2; ++amz)
                        #pragma unroll
                        for (int bo = 0; bo < 2; ++bo)
                            MMA16816F16(acc[amz][(pb + pp) * 2 + bo],
                                        ah[amz], bh2[pp][2*bo], bh2[pp][2*bo+1]);
                #pragma unroll
                for (int pp = 0; pp < 2; ++pp)
                    #pragma unroll
                    for (int amz = 0; amz < 2; ++amz)
                        #pragma unroll
                        for (int bo = 0; bo < 2; ++bo)
                            MMA16816F16(acc[amz][(pb + pp) * 2 + bo],
                                        ah[amz], bl2[pp][2*bo], bl2[pp][2*bo+1]);
                #pragma unroll
                for (int pp = 0; pp < 2; ++pp)
                    #pragma unroll
                    for (int amz = 0; amz < 2; ++amz)
                        #pragma unroll
                        for (int bo = 0; bo < 2; ++bo)
                            MMA16816F16(acc[amz][(pb + pp) * 2 + bo],
                                        al[amz], bh2[pp][2*bo], bh2[pp][2*bo+1]);
            }

            // mid-loop A split: LDG latency covered by ks=0,1; pf dies here
            if (ks == 1 && c + 1 < NCHU) splitStsA(c + 1);
        }

        if (c & 1) {
            #pragma unroll
            for (int a = 0; a < 2; a++)
                #pragma unroll
                for (int n = 0; n < 8; n++)
                    #pragma unroll
                    for (int r = 0; r < 4; r++)
                        fast2sum(hiv[a][n][r], acc[a][n][r]);
        }
    }

    // ---- write this K-quarter's partial (undo W scale) ----
    float* pout = g_part + (size_t)ksp * NTOK * NEXP;
    #pragma unroll
    for (int amz = 0; amz < 2; ++amz) {
        const int token = bm * BM + warp_m * 32 + amz * 16 + (lane >> 2);
        #pragma unroll
        for (int n = 0; n < 8; ++n) {
            const int expert = bn * BN + warp_n * 64 + n * 8 + (lane & 3) * 2;
            float d0 = (hiv[amz][n][0] + acc[amz][n][0]) * INV_SCALE;
            float d1 = (hiv[amz][n][1] + acc[amz][n][1]) * INV_SCALE;
            float d2 = (hiv[amz][n][2] + acc[amz][n][2]) * INV_SCALE;
            float d3 = (hiv[amz][n][3] + acc[amz][n][3]) * INV_SCALE;
            *reinterpret_cast<float2*>(&pout[(size_t)token * NEXP + expert]) =
                make_float2(d0, d1);
            *reinterpret_cast<float2*>(&pout[(size_t)(token + 8) * NEXP + expert]) =
                make_float2(d2, d3);
        }
    }
}

// ---------------------------------------------------------------------------
// Accurate exp (~2 ulp), immune to fast-math.
// ---------------------------------------------------------------------------
__device__ __forceinline__ float exp_acc(float xin) {
    float xc = fminf(fmaxf(xin, -30.0f), 30.0f);
    float k = rintf(xc * 1.4426950408889634f);
    float r = fmaf(k, -0.693359375f, xc);
    r = fmaf(k, 2.12194440054690e-4f, r);
    float p = 1.98412698e-4f;
    p = fmaf(p, r, 1.38888889e-3f);
    p = fmaf(p, r, 8.33333333e-3f);
    p = fmaf(p, r, 4.16666667e-2f);
    p = fmaf(p, r, 1.66666667e-1f);
    p = fmaf(p, r, 5.0e-1f);
    p = fmaf(p, r, 1.0f);
    p = fmaf(p, r, 1.0f);
    int ik = (int)k;
    float sc2 = __int_as_float((ik + 127) << 23);
    return p * sc2;
}

// ---------------------------------------------------------------------------
// Epilogue: WARP per token; sums the 4 K-split partials inline.
// ---------------------------------------------------------------------------
__global__ void __launch_bounds__(256)
gate_epilogue_warp(const float* __restrict__ bias,
                   float* __restrict__ out_w,
                   float* __restrict__ out_idx,
                   int write_idx)
{
    const unsigned FULL = 0xffffffffu;
    const int warp = threadIdx.x >> 5;
    const int lane = threadIdx.x & 31;
    const int t = blockIdx.x * 8 + warp;

    const size_t rowoff = (size_t)t * NEXP + lane * 8;
    const size_t PSTRIDE = (size_t)NTOK * NEXP;
    float4 a0 = *reinterpret_cast<const float4*>(g_part + rowoff);
    float4 a1 = *reinterpret_cast<const float4*>(g_part + rowoff + 4);
    float4 b0 = *reinterpret_cast<const float4*>(g_part + PSTRIDE + rowoff);
    float4 b1 = *reinterpret_cast<const float4*>(g_part + PSTRIDE + rowoff + 4);
    float4 c0 = *reinterpret_cast<const float4*>(g_part + 2 * PSTRIDE + rowoff);
    float4 c1 = *reinterpret_cast<const float4*>(g_part + 2 * PSTRIDE + rowoff + 4);
    float4 d0 = *reinterpret_cast<const float4*>(g_part + 3 * PSTRIDE + rowoff);
    float4 d1 = *reinterpret_cast<const float4*>(g_part + 3 * PSTRIDE + rowoff + 4);

    float lg[8];
    lg[0] = (a0.x + b0.x) + (c0.x + d0.x);
    lg[1] = (a0.y + b0.y) + (c0.y + d0.y);
    lg[2] = (a0.z + b0.z) + (c0.z + d0.z);
    lg[3] = (a0.w + b0.w) + (c0.w + d0.w);
    lg[4] = (a1.x + b1.x) + (c1.x + d1.x);
    lg[5] = (a1.y + b1.y) + (c1.y + d1.y);
    lg[6] = (a1.z + b1.z) + (c1.z + d1.z);
    lg[7] = (a1.w + b1.w) + (c1.w + d1.w);

    float4 bb0 = *reinterpret_cast<const float4*>(&bias[lane * 8]);
    float4 bb1 = *reinterpret_cast<const float4*>(&bias[lane * 8 + 4]);
    float bs[8] = {bb0.x, bb0.y, bb0.z, bb0.w, bb1.x, bb1.y, bb1.z, bb1.w};

    float sc[8], s[8];
    #pragma unroll
    for (int i = 0; i < 8; i++) {
        sc[i] = __fdiv_rn(1.0f, 1.0f + exp_acc(-lg[i]));
        s[i]  = sc[i] + bs[i];
    }

    // --- per-lane top-2 of 8, then merge across the 4-lane quad (one group) ---
    float v1 = -INFINITY, v2 = -INFINITY;
    #pragma unroll
    for (int i = 0; i < 8; i++) {
        if (s[i] > v1)      { v2 = v1; v1 = s[i]; }
        else if (s[i] > v2) { v2 = s[i]; }
    }
    #pragma unroll
    for (int o = 1; o <= 2; o <<= 1) {
        float u1 = __shfl_xor_sync(FULL, v1, o);
        float u2 = __shfl_xor_sync(FULL, v2, o);
        if (u1 > v1) { v2 = fmaxf(v1, u2); v1 = u1; }
        else         { v2 = fmaxf(v2, u1); }
    }
    const float gs = v1 + v2;       // all lanes of the quad agree

    // --- top-4 groups via rank (ties -> lower group index) ---
    float gv[8];
    #pragma unroll
    for (int g = 0; g < 8; g++) gv[g] = __shfl_sync(FULL, gs, g * 4);
    const int g0 = lane >> 2;
    int rank = 0;
    #pragma unroll
    for (int g = 0; g < 8; g++)
        rank += (gv[g] > gv[g0]) || (gv[g] == gv[g0] && g < g0);
    const bool keep = (rank < TOPG);

    float mv[8];
    #pragma unroll
    for (int i = 0; i < 8; i++) mv[i] = keep ? s[i] : -INFINITY;

    // --- masked top-8 (value desc, index asc) ---
    unsigned live = 0xffu;
    float rsc[8]; int ridx[8];
    float wsum = 0.0f;
    #pragma unroll
    for (int r = 0; r < TOPKN; r++) {
        float bv = -INFINITY, bsc2 = 0.0f;
        int bi = -1;
        #pragma unroll
        for (int i = 0; i < 8; i++) {
            if (((live >> i) & 1u) && mv[i] > bv) { bv = mv[i]; bsc2 = sc[i]; bi = i; }
        }
        int gidx = (bi >= 0) ? (lane * 8 + bi) : (1 << 30);
        float cv = bv, csc = bsc2;
        int ci = gidx;
        #pragma unroll
        for (int o = 16; o > 0; o >>= 1) {
            float ov  = __shfl_xor_sync(FULL, cv, o);
            int   oi  = __shfl_xor_sync(FULL, ci, o);
            float osc = __shfl_xor_sync(FULL, csc, o);
            if (ov > cv || (ov == cv && oi < ci)) { cv = ov; ci = oi; csc = osc; }
        }
        rsc[r] = csc; ridx[r] = ci;
        wsum += csc;
        if (lane == (ci >> 3)) live &= ~(1u << (ci & 7));
    }

    #pragma unroll
    for (int r = 0; r < TOPKN; r++) {
        if (lane == r) {
            out_w[(size_t)t * TOPKN + r] = __fdiv_rn(rsc[r], wsum) * 2.5f;
            if (write_idx) out_idx[(size_t)t * TOPKN + r] = (float)ridx[r];
        }
    }
}

// ---------------------------------------------------------------------------
extern "C" void kernel_launch(void* const* d_in, const int* in_sizes, int n_in,
                              void* d_out, int out_size)
{
    const float* x    = (const float*)d_in[0];   // [T, 7168]
    const float* w    = (const float*)d_in[1];   // [256, 7168]
    const float* bias = (const float*)d_in[2];   // [256]

    const int T = in_sizes[0] / DIM;             // 16384

    __half *p_wh, *p_wl;
    cudaGetSymbolAddress((void**)&p_wh, g_wh);
    cudaGetSymbolAddress((void**)&p_wl, g_wl);

    // w only: 7.3 MB, ~8 us
    split_prep_kernel<<<256, 256>>>(w, p_wh, p_wl, W_SCALE, NEXP * DIM / 4);

    cudaFuncSetAttribute(gemm_hmma_kernel,
                         cudaFuncAttributeMaxDynamicSharedMemorySize, SMEMB);

    dim3 grid(KSPLIT, NEXP / BN, T / BM);        // (4, 2, 128): 1024 equal units
    gemm_hmma_kernel<<<grid, 256, SMEMB>>>(x);

    float* out = (float*)d_out;
    const int write_idx = (out_size >= 2 * T * TOPKN) ? 1 : 0;
    gate_epilogue_warp<<<T / 8, 256>>>(bias, out, out + (size_t)T * TOPKN, write_idx);
}